// round 9
// baseline (speedup 1.0000x reference)
#include <cuda_runtime.h>
#include <cuda_bf16.h>
#include <cstdint>

// Problem constants
#define BB   16
#define HH   64
#define WW   64
#define CC   768
#define GRP  6            // heads per axis group
#define MTOT (BB*HH*WW)   // 65536
#define INV_SCALE 0.125f  // 1/sqrt(64)

// ---------------------------------------------------------------------------
// Static device scratch
// ---------------------------------------------------------------------------
__device__ float g_q[MTOT * CC];
__device__ float g_k[MTOT * CC];
__device__ float g_v[MTOT * CC];
__device__ __nv_bfloat16 g_qh[MTOT * CC];
__device__ __nv_bfloat16 g_ql[MTOT * CC];
__device__ __nv_bfloat16 g_vh[MTOT * CC];
__device__ __nv_bfloat16 g_vl[MTOT * CC];
__device__ __nv_bfloat16 g_ah[MTOT * CC];
__device__ __nv_bfloat16 g_al[MTOT * CC];
// transposed split weights: [4][N=768][K=768], order q,k,v,o
__device__ __nv_bfloat16 g_wth[4][CC * CC];
__device__ __nv_bfloat16 g_wtl[4][CC * CC];

// ---------------------------------------------------------------------------
// helpers
// ---------------------------------------------------------------------------
__device__ __forceinline__ uint32_t smem_u32(const void* p) {
    uint32_t a;
    asm("{ .reg .u64 t; cvta.to.shared.u64 t, %1; cvt.u32.u64 %0, t; }"
        : "=r"(a) : "l"(p));
    return a;
}
__device__ __forceinline__ uint32_t packbf(__nv_bfloat16 a, __nv_bfloat16 b) {
    return (uint32_t)__bfloat16_as_ushort(a) |
           ((uint32_t)__bfloat16_as_ushort(b) << 16);
}
__device__ __forceinline__ void cp16(uint32_t dst, const void* src) {
    asm volatile("cp.async.cg.shared.global [%0], [%1], 16;"
                 :: "r"(dst), "l"(src) : "memory");
}
__device__ __forceinline__ void ldsm4(uint32_t* r, uint32_t addr) {
    asm volatile("ldmatrix.sync.aligned.m8n8.x4.shared.b16 {%0,%1,%2,%3}, [%4];"
                 : "=r"(r[0]), "=r"(r[1]), "=r"(r[2]), "=r"(r[3]) : "r"(addr));
}
__device__ __forceinline__ void mma16816(float* d, const uint32_t* a,
                                         const uint32_t* b) {
    asm volatile(
        "mma.sync.aligned.m16n8k16.row.col.f32.bf16.bf16.f32 "
        "{%0,%1,%2,%3}, {%4,%5,%6,%7}, {%8,%9}, {%0,%1,%2,%3};"
        : "+f"(d[0]), "+f"(d[1]), "+f"(d[2]), "+f"(d[3])
        : "r"(a[0]), "r"(a[1]), "r"(a[2]), "r"(a[3]), "r"(b[0]), "r"(b[1]));
}

// ---------------------------------------------------------------------------
// Split conversion: fp32 -> bf16 hi + bf16 lo. Dual-source single launch.
// ---------------------------------------------------------------------------
__global__ void conv_split2(const float4* __restrict__ x0, uint2* __restrict__ h0,
                            uint2* __restrict__ l0,
                            const float4* __restrict__ x1, uint2* __restrict__ h1,
                            uint2* __restrict__ l1, int n4) {
    int i = blockIdx.x * blockDim.x + threadIdx.x;
    const float4* x; uint2 *h, *l;
    if (i >= n4) {
        i -= n4;
        if (i >= n4) return;
        x = x1; h = h1; l = l1;
    } else { x = x0; h = h0; l = l0; }
    float4 v = x[i];
    __nv_bfloat16 h0_ = __float2bfloat16(v.x), h1_ = __float2bfloat16(v.y);
    __nv_bfloat16 h2_ = __float2bfloat16(v.z), h3_ = __float2bfloat16(v.w);
    __nv_bfloat16 l0_ = __float2bfloat16(v.x - __bfloat162float(h0_));
    __nv_bfloat16 l1_ = __float2bfloat16(v.y - __bfloat162float(h1_));
    __nv_bfloat16 l2_ = __float2bfloat16(v.z - __bfloat162float(h2_));
    __nv_bfloat16 l3_ = __float2bfloat16(v.w - __bfloat162float(h3_));
    h[i] = make_uint2(packbf(h0_, h1_), packbf(h2_, h3_));
    l[i] = make_uint2(packbf(l0_, l1_), packbf(l2_, l3_));
}

// ---------------------------------------------------------------------------
// Weight transpose + split: W[K=768][N=768] -> Th/Tl [N=768][K=768] bf16
// ---------------------------------------------------------------------------
__global__ void wt_split(const float* __restrict__ W, __nv_bfloat16* __restrict__ Th,
                         __nv_bfloat16* __restrict__ Tl) {
    __shared__ float t[32][33];
    int nb = blockIdx.x * 32, kb = blockIdx.y * 32;
    int tx = threadIdx.x, ty = threadIdx.y;
    #pragma unroll
    for (int j = 0; j < 32; j += 8)
        t[ty + j][tx] = W[(size_t)(kb + ty + j) * CC + nb + tx];
    __syncthreads();
    #pragma unroll
    for (int j = 0; j < 32; j += 8) {
        float v = t[tx][ty + j];   // = W[kb+tx][nb+ty+j]
        __nv_bfloat16 h = __float2bfloat16(v);
        __nv_bfloat16 l = __float2bfloat16(v - __bfloat162float(h));
        size_t o = (size_t)(nb + ty + j) * CC + kb + tx;
        Th[o] = h;
        Tl[o] = l;
    }
}

// ---------------------------------------------------------------------------
// mma.sync bf16 split GEMM: C[M,N] = (Ah+Al)[M,K]*(Bh+Bl)^T[N,K] + bias[N]
// CTA tile 128x128, BK=64 elems (128B rows), 3-stage cp.async.
// 512 threads (16 warps, 4Mx4N, warp tile 32x32) for HMMA latency hiding.
// rows padded to 144B -> ldmatrix conflict-free.
// Triple-segment: grid.x = nseg*NBX; segment sel picks (A,B,bias,C) set, so
// up to 3 GEMMs run in one launch (shared waves, single tail).
// ---------------------------------------------------------------------------
#define NS       3
#define ROWB     144                    // padded row stride in bytes (128 data)
#define TILEB    (128 * ROWB)           // 18432 B per tile
#define STAGEB   (4 * TILEB)            // Ah, Al, Bh, Bl = 73728 B
#define GEMM_SMEM (NS * STAGEB)         // 221184 B
#define NBX      (CC / 128)             // 6 N-tiles per output

struct GemmSeg {
    const __nv_bfloat16 *Ah, *Al, *Bh, *Bl;
    const float* bias;
    float* C;
};

__global__ void __launch_bounds__(512, 1) gemm_bf16s(
    GemmSeg s0_, GemmSeg s1_, GemmSeg s2_)
{
    extern __shared__ char sm_raw[];
    const uint32_t s0 = smem_u32(sm_raw);

    const int tid  = threadIdx.x;
    const int lane = tid & 31;
    const int wid  = tid >> 5;
    const int wm   = wid >> 2;          // 0..3 -> M offset wm*32
    const int wn   = wid & 3;           // 0..3 -> N offset wn*32

    const int bnx = blockIdx.x;
    const int seg = bnx / NBX;
    const int bn  = bnx - seg * NBX;
    const int bm  = blockIdx.y;
    const GemmSeg sg = (seg == 0) ? s0_ : (seg == 1 ? s1_ : s2_);
    const __nv_bfloat16* __restrict__ Ah = sg.Ah;
    const __nv_bfloat16* __restrict__ Al = sg.Al;
    const __nv_bfloat16* __restrict__ Bh = sg.Bh;
    const __nv_bfloat16* __restrict__ Bl = sg.Bl;

    const size_t arow0 = (size_t)bm * 128;
    const size_t brow0 = (size_t)bn * 128;

    // producer mapping: pu = 16B unit within 128B row (0..7), pr = row (0..63)
    const int pu = tid & 7;
    const int pr = tid >> 3;

    float acc[2][4][4];
    #pragma unroll
    for (int mt = 0; mt < 2; mt++)
        #pragma unroll
        for (int nt = 0; nt < 4; nt++)
            #pragma unroll
            for (int e = 0; e < 4; e++) acc[mt][nt][e] = 0.0f;

    // --- prefetch first NS chunks ---
    #pragma unroll
    for (int c = 0; c < NS; c++) {
        const uint32_t stg = s0 + c * STAGEB;
        const int k0 = c * 64;
        #pragma unroll
        for (int p = 0; p < 2; p++) {
            int r = pr + p * 64;
            uint32_t d = stg + r * ROWB + pu * 16;
            size_t ga = (arow0 + r) * CC + k0 + pu * 8;
            size_t gb = (brow0 + r) * CC + k0 + pu * 8;
            cp16(d,              Ah + ga);
            cp16(d + TILEB,      Al + ga);
            cp16(d + 2 * TILEB,  Bh + gb);
            cp16(d + 3 * TILEB,  Bl + gb);
        }
        asm volatile("cp.async.commit_group;" ::: "memory");
    }

    // ldmatrix lane address components (constant across chunks)
    const int a_row = wm * 32 + (lane & 15);
    const int a_k   = (lane >> 4);               // 0/1 -> k-half unit
    const int b_row = wn * 32 + ((lane & 7) | ((lane >> 4) << 3));
    const int b_k   = ((lane >> 3) & 1);

    for (int c = 0; c < 12; c++) {
        asm volatile("cp.async.wait_group %0;" :: "n"(NS - 2) : "memory");
        __syncthreads();
        const uint32_t stg = s0 + (c % NS) * STAGEB;
        const uint32_t sAh = stg;
        const uint32_t sAl = stg + TILEB;
        const uint32_t sBh = stg + 2 * TILEB;
        const uint32_t sBl = stg + 3 * TILEB;

        #pragma unroll
        for (int ks = 0; ks < 4; ks++) {
            uint32_t ah[2][4], al[2][4], bh[4][2], bl[4][2];
            #pragma unroll
            for (int mt = 0; mt < 2; mt++) {
                uint32_t ad = (uint32_t)((a_row + mt * 16) * ROWB +
                                         (ks * 2 + a_k) * 16);
                ldsm4(ah[mt], sAh + ad);
                ldsm4(al[mt], sAl + ad);
            }
            #pragma unroll
            for (int np = 0; np < 2; np++) {
                uint32_t bd = (uint32_t)((b_row + np * 16) * ROWB +
                                         (ks * 2 + b_k) * 16);
                uint32_t r[4];
                ldsm4(r, sBh + bd);
                bh[np * 2][0] = r[0]; bh[np * 2][1] = r[1];
                bh[np * 2 + 1][0] = r[2]; bh[np * 2 + 1][1] = r[3];
                ldsm4(r, sBl + bd);
                bl[np * 2][0] = r[0]; bl[np * 2][1] = r[1];
                bl[np * 2 + 1][0] = r[2]; bl[np * 2 + 1][1] = r[3];
            }
            #pragma unroll
            for (int mt = 0; mt < 2; mt++)
                #pragma unroll
                for (int nt = 0; nt < 4; nt++) {
                    mma16816(acc[mt][nt], ah[mt], bh[nt]);
                    mma16816(acc[mt][nt], ah[mt], bl[nt]);
                    mma16816(acc[mt][nt], al[mt], bh[nt]);
                }
        }
        __syncthreads();
        if (c + NS < 12) {
            const uint32_t pstg = s0 + (c % NS) * STAGEB;
            const int k0 = (c + NS) * 64;
            #pragma unroll
            for (int p = 0; p < 2; p++) {
                int r = pr + p * 64;
                uint32_t d = pstg + r * ROWB + pu * 16;
                size_t ga = (arow0 + r) * CC + k0 + pu * 8;
                size_t gb = (brow0 + r) * CC + k0 + pu * 8;
                cp16(d,             Ah + ga);
                cp16(d + TILEB,     Al + ga);
                cp16(d + 2 * TILEB, Bh + gb);
                cp16(d + 3 * TILEB, Bl + gb);
            }
        }
        asm volatile("cp.async.commit_group;" ::: "memory");
    }

    // epilogue
    const float* bp = sg.bias + bn * 128;
    float* __restrict__ C = sg.C;
    #pragma unroll
    for (int mt = 0; mt < 2; mt++) {
        int row0 = bm * 128 + wm * 32 + mt * 16 + (lane >> 2);
        #pragma unroll
        for (int nt = 0; nt < 4; nt++) {
            int col = wn * 32 + nt * 8 + (lane & 3) * 2;
            float b0 = bp[col], b1 = bp[col + 1];
            float2 v0 = make_float2(acc[mt][nt][0] + b0, acc[mt][nt][1] + b1);
            float2 v1 = make_float2(acc[mt][nt][2] + b0, acc[mt][nt][3] + b1);
            *(float2*)(C + (size_t)row0 * CC + bn * 128 + col) = v0;
            *(float2*)(C + (size_t)(row0 + 8) * CC + bn * 128 + col) = v1;
        }
    }
}

// ---------------------------------------------------------------------------
// Axial attention: one CTA per (axis, b, fixed, head). seq=64, d=64.
// Register softmax (16-lane shfl groups); P reuses the Q smem buffer.
// ---------------------------------------------------------------------------
#define ATTN_SMEM ((4096 + 4160 + 4096) * 4)   // Qs/P, Ks(65-pad), Vs

__global__ void __launch_bounds__(256) attn_kernel()
{
    extern __shared__ float smem[];
    float* Qs = smem;                 // [64][64], reused for P
    float* Ks = Qs + 4096;            // [64][65] padded
    float* Vs = Ks + 4160;            // [64][64]

    const int tid = threadIdx.x;
    int idx = blockIdx.x;
    const int axis = idx / (BB * WW * GRP);
    idx -= axis * (BB * WW * GRP);
    const int b     = idx / (WW * GRP);
    int rem         = idx - b * (WW * GRP);
    const int fixed = rem / GRP;
    const int n     = rem - fixed * GRP;

    size_t base;
    int stride;
    if (axis == 0) {
        base   = ((size_t)b * HH * WW + fixed) * CC + n * 64;
        stride = WW * CC;
    } else {
        base   = ((size_t)(b * HH + fixed)) * (size_t)(WW * CC) + (n + GRP) * 64;
        stride = CC;
    }

    // float4 loads: 1024 units of 16B
    for (int t = tid; t < 1024; t += 256) {
        int i = t >> 4, d = (t & 15) * 4;
        size_t off = base + (size_t)i * stride + d;
        float4 q4 = *(const float4*)(g_q + off);
        float4 k4 = *(const float4*)(g_k + off);
        float4 v4 = *(const float4*)(g_v + off);
        *(float4*)(Qs + i * 64 + d) = q4;
        Ks[i * 65 + d + 0] = k4.x; Ks[i * 65 + d + 1] = k4.y;
        Ks[i * 65 + d + 2] = k4.z; Ks[i * 65 + d + 3] = k4.w;
        *(float4*)(Vs + i * 64 + d) = v4;
    }
    __syncthreads();

    const int tx = tid & 15;
    const int ty = tid >> 4;
    const int i0 = ty * 4;
    const int j0 = tx * 4;

    // S tile in registers
    float acc[4][4];
    #pragma unroll
    for (int a = 0; a < 4; a++)
        #pragma unroll
        for (int c = 0; c < 4; c++) acc[a][c] = 0.0f;
    #pragma unroll 4
    for (int d = 0; d < 64; d++) {
        float qr[4], kr[4];
        #pragma unroll
        for (int a = 0; a < 4; a++) qr[a] = Qs[(i0 + a) * 64 + d];
        #pragma unroll
        for (int c = 0; c < 4; c++) kr[c] = Ks[(j0 + c) * 65 + d];
        #pragma unroll
        for (int a = 0; a < 4; a++)
            #pragma unroll
            for (int c = 0; c < 4; c++)
                acc[a][c] = fmaf(qr[a], kr[c], acc[a][c]);
    }

    // register softmax per row (16-lane groups)
    #pragma unroll
    for (int a = 0; a < 4; a++) {
        float m = fmaxf(fmaxf(acc[a][0], acc[a][1]), fmaxf(acc[a][2], acc[a][3]));
        #pragma unroll
        for (int o = 8; o > 0; o >>= 1)
            m = fmaxf(m, __shfl_xor_sync(0xffffffffu, m, o));
        float e0 = __expf((acc[a][0] - m) * INV_SCALE);
        float e1 = __expf((acc[a][1] - m) * INV_SCALE);
        float e2 = __expf((acc[a][2] - m) * INV_SCALE);
        float e3 = __expf((acc[a][3] - m) * INV_SCALE);
        float s = e0 + e1 + e2 + e3;
        #pragma unroll
        for (int o = 8; o > 0; o >>= 1)
            s += __shfl_xor_sync(0xffffffffu, s, o);
        float inv = 1.0f / s;
        acc[a][0] = e0 * inv; acc[a][1] = e1 * inv;
        acc[a][2] = e2 * inv; acc[a][3] = e3 * inv;
    }

    __syncthreads();   // all Qs/Ks reads done -> safe to overwrite Qs with P
    #pragma unroll
    for (int a = 0; a < 4; a++)
        *(float4*)(Qs + (i0 + a) * 64 + j0) =
            make_float4(acc[a][0], acc[a][1], acc[a][2], acc[a][3]);
    __syncthreads();

    // O = P V
    {
        float o_[4][4];
        #pragma unroll
        for (int a = 0; a < 4; a++)
            #pragma unroll
            for (int c = 0; c < 4; c++) o_[a][c] = 0.0f;
        #pragma unroll 4
        for (int j = 0; j < 64; j++) {
            float pr[4], vr[4];
            #pragma unroll
            for (int a = 0; a < 4; a++) pr[a] = Qs[(i0 + a) * 64 + j];
            #pragma unroll
            for (int c = 0; c < 4; c++) vr[c] = Vs[j * 64 + j0 + c];
            #pragma unroll
            for (int a = 0; a < 4; a++)
                #pragma unroll
                for (int c = 0; c < 4; c++)
                    o_[a][c] = fmaf(pr[a], vr[c], o_[a][c]);
        }
        #pragma unroll
        for (int a = 0; a < 4; a++) {
            size_t off = base + (size_t)(i0 + a) * stride + j0;
            __nv_bfloat16 h[4], l[4];
            #pragma unroll
            for (int c = 0; c < 4; c++) {
                h[c] = __float2bfloat16(o_[a][c]);
                l[c] = __float2bfloat16(o_[a][c] - __bfloat162float(h[c]));
            }
            *(uint2*)(g_ah + off) = make_uint2(packbf(h[0], h[1]), packbf(h[2], h[3]));
            *(uint2*)(g_al + off) = make_uint2(packbf(l[0], l[1]), packbf(l[2], l[3]));
        }
    }
}

// ---------------------------------------------------------------------------
extern "C" void kernel_launch(void* const* d_in, const int* in_sizes, int n_in,
                              void* d_out, int out_size)
{
    const float* queries = (const float*)d_in[0];
    const float* values  = (const float*)d_in[1];
    const float* Wq = (const float*)d_in[2];
    const float* bq = (const float*)d_in[3];
    const float* Wk = (const float*)d_in[4];
    const float* bk = (const float*)d_in[5];
    const float* Wv = (const float*)d_in[6];
    const float* bv = (const float*)d_in[7];
    const float* Wo = (const float*)d_in[8];
    const float* bo = (const float*)d_in[9];
    float* out = (float*)d_out;

    float *qp, *kp, *vp;
    __nv_bfloat16 *qh, *ql, *vh, *vl, *ah, *al, *wth, *wtl;
    cudaGetSymbolAddress((void**)&qp, g_q);
    cudaGetSymbolAddress((void**)&kp, g_k);
    cudaGetSymbolAddress((void**)&vp, g_v);
    cudaGetSymbolAddress((void**)&qh, g_qh);
    cudaGetSymbolAddress((void**)&ql, g_ql);
    cudaGetSymbolAddress((void**)&vh, g_vh);
    cudaGetSymbolAddress((void**)&vl, g_vl);
    cudaGetSymbolAddress((void**)&ah, g_ah);
    cudaGetSymbolAddress((void**)&al, g_al);
    cudaGetSymbolAddress((void**)&wth, g_wth);
    cudaGetSymbolAddress((void**)&wtl, g_wtl);

    cudaFuncSetAttribute(attn_kernel, cudaFuncAttributeMaxDynamicSharedMemorySize,
                         ATTN_SMEM);
    cudaFuncSetAttribute(gemm_bf16s, cudaFuncAttributeMaxDynamicSharedMemorySize,
                         GEMM_SMEM);

    const int n4 = MTOT * CC / 4;

    // input split conversions (both tensors, one launch)
    conv_split2<<<(2 * n4 + 255) / 256, 256>>>(
        (const float4*)queries, (uint2*)qh, (uint2*)ql,
        (const float4*)values,  (uint2*)vh, (uint2*)vl, n4);

    // weight transpose + split
    dim3 wtg(CC / 32, CC / 32), wtb(32, 8);
    __nv_bfloat16* WqH = wth + 0 * (size_t)CC * CC; __nv_bfloat16* WqL = wtl + 0 * (size_t)CC * CC;
    __nv_bfloat16* WkH = wth + 1 * (size_t)CC * CC; __nv_bfloat16* WkL = wtl + 1 * (size_t)CC * CC;
    __nv_bfloat16* WvH = wth + 2 * (size_t)CC * CC; __nv_bfloat16* WvL = wtl + 2 * (size_t)CC * CC;
    __nv_bfloat16* WoH = wth + 3 * (size_t)CC * CC; __nv_bfloat16* WoL = wtl + 3 * (size_t)CC * CC;
    wt_split<<<wtg, wtb>>>(Wq, WqH, WqL);
    wt_split<<<wtg, wtb>>>(Wk, WkH, WkL);
    wt_split<<<wtg, wtb>>>(Wv, WvH, WvL);
    wt_split<<<wtg, wtb>>>(Wo, WoH, WoL);

    // Q, K, V projections fused into one launch (3 segments)
    GemmSeg sq = {qh, ql, WqH, WqL, bq, qp};
    GemmSeg sk = {vh, vl, WkH, WkL, bk, kp};
    GemmSeg sv = {vh, vl, WvH, WvL, bv, vp};
    dim3 g3(3 * NBX, MTOT / 128);
    gemm_bf16s<<<g3, 512, GEMM_SMEM>>>(sq, sk, sv);

    attn_kernel<<<2 * BB * WW * GRP, 256, ATTN_SMEM>>>();

    // output projection
    GemmSeg so = {ah, al, WoH, WoL, bo, out};
    dim3 g1(NBX, MTOT / 128);
    gemm_bf16s<<<g1, 512, GEMM_SMEM>>>(so, so, so);
}

// round 10
// speedup vs baseline: 1.0341x; 1.0341x over previous
#include <cuda_runtime.h>
#include <cuda_bf16.h>
#include <cstdint>

// Problem constants
#define BB   16
#define HH   64
#define WW   64
#define CC   768
#define GRP  6            // heads per axis group
#define MTOT (BB*HH*WW)   // 65536
#define INV_SCALE 0.125f  // 1/sqrt(64)

// ---------------------------------------------------------------------------
// Static device scratch
// ---------------------------------------------------------------------------
__device__ float g_q[MTOT * CC];
__device__ float g_k[MTOT * CC];
__device__ float g_v[MTOT * CC];
__device__ __nv_bfloat16 g_qh[MTOT * CC];
__device__ __nv_bfloat16 g_ql[MTOT * CC];
__device__ __nv_bfloat16 g_vh[MTOT * CC];
__device__ __nv_bfloat16 g_vl[MTOT * CC];
__device__ __nv_bfloat16 g_ah[MTOT * CC];
__device__ __nv_bfloat16 g_al[MTOT * CC];
// transposed split weights: [4][N=768][K=768], order q,k,v,o
__device__ __nv_bfloat16 g_wth[4][CC * CC];
__device__ __nv_bfloat16 g_wtl[4][CC * CC];

// ---------------------------------------------------------------------------
// helpers
// ---------------------------------------------------------------------------
__device__ __forceinline__ uint32_t smem_u32(const void* p) {
    uint32_t a;
    asm("{ .reg .u64 t; cvta.to.shared.u64 t, %1; cvt.u32.u64 %0, t; }"
        : "=r"(a) : "l"(p));
    return a;
}
__device__ __forceinline__ uint32_t packbf(__nv_bfloat16 a, __nv_bfloat16 b) {
    return (uint32_t)__bfloat16_as_ushort(a) |
           ((uint32_t)__bfloat16_as_ushort(b) << 16);
}
__device__ __forceinline__ void cp16(uint32_t dst, const void* src) {
    asm volatile("cp.async.cg.shared.global [%0], [%1], 16;"
                 :: "r"(dst), "l"(src) : "memory");
}
__device__ __forceinline__ void ldsm4(uint32_t* r, uint32_t addr) {
    asm volatile("ldmatrix.sync.aligned.m8n8.x4.shared.b16 {%0,%1,%2,%3}, [%4];"
                 : "=r"(r[0]), "=r"(r[1]), "=r"(r[2]), "=r"(r[3]) : "r"(addr));
}
__device__ __forceinline__ void mma16816(float* d, const uint32_t* a,
                                         const uint32_t* b) {
    asm volatile(
        "mma.sync.aligned.m16n8k16.row.col.f32.bf16.bf16.f32 "
        "{%0,%1,%2,%3}, {%4,%5,%6,%7}, {%8,%9}, {%0,%1,%2,%3};"
        : "+f"(d[0]), "+f"(d[1]), "+f"(d[2]), "+f"(d[3])
        : "r"(a[0]), "r"(a[1]), "r"(a[2]), "r"(a[3]), "r"(b[0]), "r"(b[1]));
}

// ---------------------------------------------------------------------------
// Split conversion: fp32 -> bf16 hi + bf16 lo. Dual-source single launch.
// ---------------------------------------------------------------------------
__global__ void conv_split2(const float4* __restrict__ x0, uint2* __restrict__ h0,
                            uint2* __restrict__ l0,
                            const float4* __restrict__ x1, uint2* __restrict__ h1,
                            uint2* __restrict__ l1, int n4) {
    int i = blockIdx.x * blockDim.x + threadIdx.x;
    const float4* x; uint2 *h, *l;
    if (i >= n4) {
        i -= n4;
        if (i >= n4) return;
        x = x1; h = h1; l = l1;
    } else { x = x0; h = h0; l = l0; }
    float4 v = x[i];
    __nv_bfloat16 h0_ = __float2bfloat16(v.x), h1_ = __float2bfloat16(v.y);
    __nv_bfloat16 h2_ = __float2bfloat16(v.z), h3_ = __float2bfloat16(v.w);
    __nv_bfloat16 l0_ = __float2bfloat16(v.x - __bfloat162float(h0_));
    __nv_bfloat16 l1_ = __float2bfloat16(v.y - __bfloat162float(h1_));
    __nv_bfloat16 l2_ = __float2bfloat16(v.z - __bfloat162float(h2_));
    __nv_bfloat16 l3_ = __float2bfloat16(v.w - __bfloat162float(h3_));
    h[i] = make_uint2(packbf(h0_, h1_), packbf(h2_, h3_));
    l[i] = make_uint2(packbf(l0_, l1_), packbf(l2_, l3_));
}

// ---------------------------------------------------------------------------
// Weight transpose + split: W[K=768][N=768] -> Th/Tl [N=768][K=768] bf16
// ---------------------------------------------------------------------------
__global__ void wt_split(const float* __restrict__ W, __nv_bfloat16* __restrict__ Th,
                         __nv_bfloat16* __restrict__ Tl) {
    __shared__ float t[32][33];
    int nb = blockIdx.x * 32, kb = blockIdx.y * 32;
    int tx = threadIdx.x, ty = threadIdx.y;
    #pragma unroll
    for (int j = 0; j < 32; j += 8)
        t[ty + j][tx] = W[(size_t)(kb + ty + j) * CC + nb + tx];
    __syncthreads();
    #pragma unroll
    for (int j = 0; j < 32; j += 8) {
        float v = t[tx][ty + j];   // = W[kb+tx][nb+ty+j]
        __nv_bfloat16 h = __float2bfloat16(v);
        __nv_bfloat16 l = __float2bfloat16(v - __bfloat162float(h));
        size_t o = (size_t)(nb + ty + j) * CC + kb + tx;
        Th[o] = h;
        Tl[o] = l;
    }
}

// ---------------------------------------------------------------------------
// mma.sync bf16 split GEMM: C[M,N] = (Ah+Al)[M,K]*(Bh+Bl)^T[N,K] + bias[N]
// CTA tile 128x128, BK=64 elems (128B rows), 3-stage cp.async.
// 256 threads (8 warps, 4Mx2N, warp tile 32x64). rows padded to 144B.
// Triple-segment: grid.x = nseg*NBX; per-block segment select, so up to 3
// GEMMs run in one launch (shared waves, single tail).
// ---------------------------------------------------------------------------
#define NS       3
#define ROWB     144                    // padded row stride in bytes (128 data)
#define TILEB    (128 * ROWB)           // 18432 B per tile
#define STAGEB   (4 * TILEB)            // Ah, Al, Bh, Bl = 73728 B
#define GEMM_SMEM (NS * STAGEB)         // 221184 B
#define NBX      (CC / 128)             // 6 N-tiles per output

struct GemmSeg {
    const __nv_bfloat16 *Ah, *Al, *Bh, *Bl;
    const float* bias;
    float* C;
};

__global__ void __launch_bounds__(256, 1) gemm_bf16s(
    GemmSeg s0_, GemmSeg s1_, GemmSeg s2_)
{
    extern __shared__ char sm_raw[];
    const uint32_t s0 = smem_u32(sm_raw);

    const int tid  = threadIdx.x;
    const int lane = tid & 31;
    const int wid  = tid >> 5;
    const int wm   = wid >> 1;          // 0..3 -> M offset wm*32
    const int wn   = wid & 1;           // 0..1 -> N offset wn*64

    const int bnx = blockIdx.x;
    const int seg = bnx / NBX;
    const int bn  = bnx - seg * NBX;
    const int bm  = blockIdx.y;
    const GemmSeg sg = (seg == 0) ? s0_ : (seg == 1 ? s1_ : s2_);
    const __nv_bfloat16* __restrict__ Ah = sg.Ah;
    const __nv_bfloat16* __restrict__ Al = sg.Al;
    const __nv_bfloat16* __restrict__ Bh = sg.Bh;
    const __nv_bfloat16* __restrict__ Bl = sg.Bl;

    const size_t arow0 = (size_t)bm * 128;
    const size_t brow0 = (size_t)bn * 128;

    // producer mapping: pu = 16B unit within 128B row (0..7), pr = row (0..31)
    const int pu = tid & 7;
    const int pr = tid >> 3;

    float acc[2][8][4];
    #pragma unroll
    for (int mt = 0; mt < 2; mt++)
        #pragma unroll
        for (int nt = 0; nt < 8; nt++)
            #pragma unroll
            for (int e = 0; e < 4; e++) acc[mt][nt][e] = 0.0f;

    // --- prefetch first NS chunks ---
    #pragma unroll
    for (int c = 0; c < NS; c++) {
        const uint32_t stg = s0 + c * STAGEB;
        const int k0 = c * 64;
        #pragma unroll
        for (int p = 0; p < 4; p++) {
            int r = pr + p * 32;
            uint32_t d = stg + r * ROWB + pu * 16;
            size_t ga = (arow0 + r) * CC + k0 + pu * 8;
            size_t gb = (brow0 + r) * CC + k0 + pu * 8;
            cp16(d,              Ah + ga);
            cp16(d + TILEB,      Al + ga);
            cp16(d + 2 * TILEB,  Bh + gb);
            cp16(d + 3 * TILEB,  Bl + gb);
        }
        asm volatile("cp.async.commit_group;" ::: "memory");
    }

    // ldmatrix lane address components (constant across chunks)
    const int a_row = wm * 32 + (lane & 15);
    const int a_k   = (lane >> 4);               // 0/1 -> k-half unit
    const int b_row = wn * 64 + ((lane & 7) | ((lane >> 4) << 3));
    const int b_k   = ((lane >> 3) & 1);

    for (int c = 0; c < 12; c++) {
        asm volatile("cp.async.wait_group %0;" :: "n"(NS - 2) : "memory");
        __syncthreads();
        const uint32_t stg = s0 + (c % NS) * STAGEB;
        const uint32_t sAh = stg;
        const uint32_t sAl = stg + TILEB;
        const uint32_t sBh = stg + 2 * TILEB;
        const uint32_t sBl = stg + 3 * TILEB;

        #pragma unroll
        for (int ks = 0; ks < 4; ks++) {
            uint32_t ah[2][4], al[2][4], bh[8][2], bl[8][2];
            #pragma unroll
            for (int mt = 0; mt < 2; mt++) {
                uint32_t ad = (uint32_t)((a_row + mt * 16) * ROWB +
                                         (ks * 2 + a_k) * 16);
                ldsm4(ah[mt], sAh + ad);
                ldsm4(al[mt], sAl + ad);
            }
            #pragma unroll
            for (int np = 0; np < 4; np++) {
                uint32_t bd = (uint32_t)((b_row + np * 16) * ROWB +
                                         (ks * 2 + b_k) * 16);
                uint32_t r[4];
                ldsm4(r, sBh + bd);
                bh[np * 2][0] = r[0]; bh[np * 2][1] = r[1];
                bh[np * 2 + 1][0] = r[2]; bh[np * 2 + 1][1] = r[3];
                ldsm4(r, sBl + bd);
                bl[np * 2][0] = r[0]; bl[np * 2][1] = r[1];
                bl[np * 2 + 1][0] = r[2]; bl[np * 2 + 1][1] = r[3];
            }
            #pragma unroll
            for (int mt = 0; mt < 2; mt++)
                #pragma unroll
                for (int nt = 0; nt < 8; nt++) {
                    mma16816(acc[mt][nt], ah[mt], bh[nt]);
                    mma16816(acc[mt][nt], ah[mt], bl[nt]);
                    mma16816(acc[mt][nt], al[mt], bh[nt]);
                }
        }
        __syncthreads();
        if (c + NS < 12) {
            const uint32_t pstg = s0 + (c % NS) * STAGEB;
            const int k0 = (c + NS) * 64;
            #pragma unroll
            for (int p = 0; p < 4; p++) {
                int r = pr + p * 32;
                uint32_t d = pstg + r * ROWB + pu * 16;
                size_t ga = (arow0 + r) * CC + k0 + pu * 8;
                size_t gb = (brow0 + r) * CC + k0 + pu * 8;
                cp16(d,             Ah + ga);
                cp16(d + TILEB,     Al + ga);
                cp16(d + 2 * TILEB, Bh + gb);
                cp16(d + 3 * TILEB, Bl + gb);
            }
        }
        asm volatile("cp.async.commit_group;" ::: "memory");
    }

    // epilogue
    const float* bp = sg.bias + bn * 128;
    float* __restrict__ C = sg.C;
    #pragma unroll
    for (int mt = 0; mt < 2; mt++) {
        int row0 = bm * 128 + wm * 32 + mt * 16 + (lane >> 2);
        #pragma unroll
        for (int nt = 0; nt < 8; nt++) {
            int col = wn * 64 + nt * 8 + (lane & 3) * 2;
            float b0 = bp[col], b1 = bp[col + 1];
            float2 v0 = make_float2(acc[mt][nt][0] + b0, acc[mt][nt][1] + b1);
            float2 v1 = make_float2(acc[mt][nt][2] + b0, acc[mt][nt][3] + b1);
            *(float2*)(C + (size_t)row0 * CC + bn * 128 + col) = v0;
            *(float2*)(C + (size_t)(row0 + 8) * CC + bn * 128 + col) = v1;
        }
    }
}

// ---------------------------------------------------------------------------
// Axial attention: one CTA per (axis, b, fixed, head). seq=64, d=64.
// Register softmax (16-lane shfl groups); P reuses the Q smem buffer.
// ---------------------------------------------------------------------------
#define ATTN_SMEM ((4096 + 4160 + 4096) * 4)   // Qs/P, Ks(65-pad), Vs

__global__ void __launch_bounds__(256) attn_kernel()
{
    extern __shared__ float smem[];
    float* Qs = smem;                 // [64][64], reused for P
    float* Ks = Qs + 4096;            // [64][65] padded
    float* Vs = Ks + 4160;            // [64][64]

    const int tid = threadIdx.x;
    int idx = blockIdx.x;
    const int axis = idx / (BB * WW * GRP);
    idx -= axis * (BB * WW * GRP);
    const int b     = idx / (WW * GRP);
    int rem         = idx - b * (WW * GRP);
    const int fixed = rem / GRP;
    const int n     = rem - fixed * GRP;

    size_t base;
    int stride;
    if (axis == 0) {
        base   = ((size_t)b * HH * WW + fixed) * CC + n * 64;
        stride = WW * CC;
    } else {
        base   = ((size_t)(b * HH + fixed)) * (size_t)(WW * CC) + (n + GRP) * 64;
        stride = CC;
    }

    // float4 loads: 1024 units of 16B
    for (int t = tid; t < 1024; t += 256) {
        int i = t >> 4, d = (t & 15) * 4;
        size_t off = base + (size_t)i * stride + d;
        float4 q4 = *(const float4*)(g_q + off);
        float4 k4 = *(const float4*)(g_k + off);
        float4 v4 = *(const float4*)(g_v + off);
        *(float4*)(Qs + i * 64 + d) = q4;
        Ks[i * 65 + d + 0] = k4.x; Ks[i * 65 + d + 1] = k4.y;
        Ks[i * 65 + d + 2] = k4.z; Ks[i * 65 + d + 3] = k4.w;
        *(float4*)(Vs + i * 64 + d) = v4;
    }
    __syncthreads();

    const int tx = tid & 15;
    const int ty = tid >> 4;
    const int i0 = ty * 4;
    const int j0 = tx * 4;

    // S tile in registers
    float acc[4][4];
    #pragma unroll
    for (int a = 0; a < 4; a++)
        #pragma unroll
        for (int c = 0; c < 4; c++) acc[a][c] = 0.0f;
    #pragma unroll 4
    for (int d = 0; d < 64; d++) {
        float qr[4], kr[4];
        #pragma unroll
        for (int a = 0; a < 4; a++) qr[a] = Qs[(i0 + a) * 64 + d];
        #pragma unroll
        for (int c = 0; c < 4; c++) kr[c] = Ks[(j0 + c) * 65 + d];
        #pragma unroll
        for (int a = 0; a < 4; a++)
            #pragma unroll
            for (int c = 0; c < 4; c++)
                acc[a][c] = fmaf(qr[a], kr[c], acc[a][c]);
    }

    // register softmax per row (16-lane groups)
    #pragma unroll
    for (int a = 0; a < 4; a++) {
        float m = fmaxf(fmaxf(acc[a][0], acc[a][1]), fmaxf(acc[a][2], acc[a][3]));
        #pragma unroll
        for (int o = 8; o > 0; o >>= 1)
            m = fmaxf(m, __shfl_xor_sync(0xffffffffu, m, o));
        float e0 = __expf((acc[a][0] - m) * INV_SCALE);
        float e1 = __expf((acc[a][1] - m) * INV_SCALE);
        float e2 = __expf((acc[a][2] - m) * INV_SCALE);
        float e3 = __expf((acc[a][3] - m) * INV_SCALE);
        float s = e0 + e1 + e2 + e3;
        #pragma unroll
        for (int o = 8; o > 0; o >>= 1)
            s += __shfl_xor_sync(0xffffffffu, s, o);
        float inv = 1.0f / s;
        acc[a][0] = e0 * inv; acc[a][1] = e1 * inv;
        acc[a][2] = e2 * inv; acc[a][3] = e3 * inv;
    }

    __syncthreads();   // all Qs/Ks reads done -> safe to overwrite Qs with P
    #pragma unroll
    for (int a = 0; a < 4; a++)
        *(float4*)(Qs + (i0 + a) * 64 + j0) =
            make_float4(acc[a][0], acc[a][1], acc[a][2], acc[a][3]);
    __syncthreads();

    // O = P V
    {
        float o_[4][4];
        #pragma unroll
        for (int a = 0; a < 4; a++)
            #pragma unroll
            for (int c = 0; c < 4; c++) o_[a][c] = 0.0f;
        #pragma unroll 4
        for (int j = 0; j < 64; j++) {
            float pr[4], vr[4];
            #pragma unroll
            for (int a = 0; a < 4; a++) pr[a] = Qs[(i0 + a) * 64 + j];
            #pragma unroll
            for (int c = 0; c < 4; c++) vr[c] = Vs[j * 64 + j0 + c];
            #pragma unroll
            for (int a = 0; a < 4; a++)
                #pragma unroll
                for (int c = 0; c < 4; c++)
                    o_[a][c] = fmaf(pr[a], vr[c], o_[a][c]);
        }
        #pragma unroll
        for (int a = 0; a < 4; a++) {
            size_t off = base + (size_t)(i0 + a) * stride + j0;
            __nv_bfloat16 h[4], l[4];
            #pragma unroll
            for (int c = 0; c < 4; c++) {
                h[c] = __float2bfloat16(o_[a][c]);
                l[c] = __float2bfloat16(o_[a][c] - __bfloat162float(h[c]));
            }
            *(uint2*)(g_ah + off) = make_uint2(packbf(h[0], h[1]), packbf(h[2], h[3]));
            *(uint2*)(g_al + off) = make_uint2(packbf(l[0], l[1]), packbf(l[2], l[3]));
        }
    }
}

// ---------------------------------------------------------------------------
extern "C" void kernel_launch(void* const* d_in, const int* in_sizes, int n_in,
                              void* d_out, int out_size)
{
    const float* queries = (const float*)d_in[0];
    const float* values  = (const float*)d_in[1];
    const float* Wq = (const float*)d_in[2];
    const float* bq = (const float*)d_in[3];
    const float* Wk = (const float*)d_in[4];
    const float* bk = (const float*)d_in[5];
    const float* Wv = (const float*)d_in[6];
    const float* bv = (const float*)d_in[7];
    const float* Wo = (const float*)d_in[8];
    const float* bo = (const float*)d_in[9];
    float* out = (float*)d_out;

    float *qp, *kp, *vp;
    __nv_bfloat16 *qh, *ql, *vh, *vl, *ah, *al, *wth, *wtl;
    cudaGetSymbolAddress((void**)&qp, g_q);
    cudaGetSymbolAddress((void**)&kp, g_k);
    cudaGetSymbolAddress((void**)&vp, g_v);
    cudaGetSymbolAddress((void**)&qh, g_qh);
    cudaGetSymbolAddress((void**)&ql, g_ql);
    cudaGetSymbolAddress((void**)&vh, g_vh);
    cudaGetSymbolAddress((void**)&vl, g_vl);
    cudaGetSymbolAddress((void**)&ah, g_ah);
    cudaGetSymbolAddress((void**)&al, g_al);
    cudaGetSymbolAddress((void**)&wth, g_wth);
    cudaGetSymbolAddress((void**)&wtl, g_wtl);

    cudaFuncSetAttribute(attn_kernel, cudaFuncAttributeMaxDynamicSharedMemorySize,
                         ATTN_SMEM);
    cudaFuncSetAttribute(gemm_bf16s, cudaFuncAttributeMaxDynamicSharedMemorySize,
                         GEMM_SMEM);

    const int n4 = MTOT * CC / 4;

    // weight transpose + split FIRST (launches 0-3) so ncu -s 5 catches GEMM
    dim3 wtg(CC / 32, CC / 32), wtb(32, 8);
    __nv_bfloat16* WqH = wth + 0 * (size_t)CC * CC; __nv_bfloat16* WqL = wtl + 0 * (size_t)CC * CC;
    __nv_bfloat16* WkH = wth + 1 * (size_t)CC * CC; __nv_bfloat16* WkL = wtl + 1 * (size_t)CC * CC;
    __nv_bfloat16* WvH = wth + 2 * (size_t)CC * CC; __nv_bfloat16* WvL = wtl + 2 * (size_t)CC * CC;
    __nv_bfloat16* WoH = wth + 3 * (size_t)CC * CC; __nv_bfloat16* WoL = wtl + 3 * (size_t)CC * CC;
    wt_split<<<wtg, wtb>>>(Wq, WqH, WqL);
    wt_split<<<wtg, wtb>>>(Wk, WkH, WkL);
    wt_split<<<wtg, wtb>>>(Wv, WvH, WvL);
    wt_split<<<wtg, wtb>>>(Wo, WoH, WoL);

    // input split conversions (both tensors, one launch) — launch 4
    conv_split2<<<(2 * n4 + 255) / 256, 256>>>(
        (const float4*)queries, (uint2*)qh, (uint2*)ql,
        (const float4*)values,  (uint2*)vh, (uint2*)vl, n4);

    // Q, K, V projections fused into one launch (3 segments) — launch 5
    GemmSeg sq = {qh, ql, WqH, WqL, bq, qp};
    GemmSeg sk = {vh, vl, WkH, WkL, bk, kp};
    GemmSeg sv = {vh, vl, WvH, WvL, bv, vp};
    dim3 g3(3 * NBX, MTOT / 128);
    gemm_bf16s<<<g3, 256, GEMM_SMEM>>>(sq, sk, sv);

    attn_kernel<<<2 * BB * WW * GRP, 256, ATTN_SMEM>>>();

    // output projection
    GemmSeg so = {ah, al, WoH, WoL, bo, out};
    dim3 g1(NBX, MTOT / 128);
    gemm_bf16s<<<g1, 256, GEMM_SMEM>>>(so, so, so);
}

// round 13
// speedup vs baseline: 1.1206x; 1.0837x over previous
#include <cuda_runtime.h>
#include <cuda_bf16.h>
#include <cstdint>

// Problem constants
#define BB   16
#define HH   64
#define WW   64
#define CC   768
#define GRP  6            // heads per axis group
#define MTOT (BB*HH*WW)   // 65536
#define INV_SCALE 0.125f  // 1/sqrt(64)

// ---------------------------------------------------------------------------
// Static device scratch
// ---------------------------------------------------------------------------
__device__ float g_q[MTOT * CC];
__device__ float g_k[MTOT * CC];
__device__ float g_v[MTOT * CC];
__device__ __nv_bfloat16 g_qh[MTOT * CC];
__device__ __nv_bfloat16 g_ql[MTOT * CC];
__device__ __nv_bfloat16 g_vh[MTOT * CC];
__device__ __nv_bfloat16 g_vl[MTOT * CC];
__device__ __nv_bfloat16 g_ah[MTOT * CC];
__device__ __nv_bfloat16 g_al[MTOT * CC];
// transposed split weights: [4][N=768][K=768], order q,k,v,o
__device__ __nv_bfloat16 g_wth[4][CC * CC];
__device__ __nv_bfloat16 g_wtl[4][CC * CC];

// ---------------------------------------------------------------------------
// helpers
// ---------------------------------------------------------------------------
__device__ __forceinline__ uint32_t smem_u32(const void* p) {
    uint32_t a;
    asm("{ .reg .u64 t; cvta.to.shared.u64 t, %1; cvt.u32.u64 %0, t; }"
        : "=r"(a) : "l"(p));
    return a;
}
__device__ __forceinline__ uint32_t packbf(__nv_bfloat16 a, __nv_bfloat16 b) {
    return (uint32_t)__bfloat16_as_ushort(a) |
           ((uint32_t)__bfloat16_as_ushort(b) << 16);
}
__device__ __forceinline__ void cp16(uint32_t dst, const void* src) {
    asm volatile("cp.async.cg.shared.global [%0], [%1], 16;"
                 :: "r"(dst), "l"(src) : "memory");
}
__device__ __forceinline__ void ldsm4(uint32_t* r, uint32_t addr) {
    asm volatile("ldmatrix.sync.aligned.m8n8.x4.shared.b16 {%0,%1,%2,%3}, [%4];"
                 : "=r"(r[0]), "=r"(r[1]), "=r"(r[2]), "=r"(r[3]) : "r"(addr));
}
__device__ __forceinline__ void mma16816(float* d, const uint32_t* a,
                                         const uint32_t* b) {
    asm volatile(
        "mma.sync.aligned.m16n8k16.row.col.f32.bf16.bf16.f32 "
        "{%0,%1,%2,%3}, {%4,%5,%6,%7}, {%8,%9}, {%0,%1,%2,%3};"
        : "+f"(d[0]), "+f"(d[1]), "+f"(d[2]), "+f"(d[3])
        : "r"(a[0]), "r"(a[1]), "r"(a[2]), "r"(a[3]), "r"(b[0]), "r"(b[1]));
}

// ---------------------------------------------------------------------------
// Split conversion: fp32 -> bf16 hi + bf16 lo. Dual-source single launch.
// ---------------------------------------------------------------------------
__global__ void conv_split2(const float4* __restrict__ x0, uint2* __restrict__ h0,
                            uint2* __restrict__ l0,
                            const float4* __restrict__ x1, uint2* __restrict__ h1,
                            uint2* __restrict__ l1, int n4) {
    int i = blockIdx.x * blockDim.x + threadIdx.x;
    const float4* x; uint2 *h, *l;
    if (i >= n4) {
        i -= n4;
        if (i >= n4) return;
        x = x1; h = h1; l = l1;
    } else { x = x0; h = h0; l = l0; }
    float4 v = x[i];
    __nv_bfloat16 h0_ = __float2bfloat16(v.x), h1_ = __float2bfloat16(v.y);
    __nv_bfloat16 h2_ = __float2bfloat16(v.z), h3_ = __float2bfloat16(v.w);
    __nv_bfloat16 l0_ = __float2bfloat16(v.x - __bfloat162float(h0_));
    __nv_bfloat16 l1_ = __float2bfloat16(v.y - __bfloat162float(h1_));
    __nv_bfloat16 l2_ = __float2bfloat16(v.z - __bfloat162float(h2_));
    __nv_bfloat16 l3_ = __float2bfloat16(v.w - __bfloat162float(h3_));
    h[i] = make_uint2(packbf(h0_, h1_), packbf(h2_, h3_));
    l[i] = make_uint2(packbf(l0_, l1_), packbf(l2_, l3_));
}

// ---------------------------------------------------------------------------
// Weight transpose + split: W[K=768][N=768] -> Th/Tl [N=768][K=768] bf16
// ---------------------------------------------------------------------------
__global__ void wt_split(const float* __restrict__ W, __nv_bfloat16* __restrict__ Th,
                         __nv_bfloat16* __restrict__ Tl) {
    __shared__ float t[32][33];
    int nb = blockIdx.x * 32, kb = blockIdx.y * 32;
    int tx = threadIdx.x, ty = threadIdx.y;
    #pragma unroll
    for (int j = 0; j < 32; j += 8)
        t[ty + j][tx] = W[(size_t)(kb + ty + j) * CC + nb + tx];
    __syncthreads();
    #pragma unroll
    for (int j = 0; j < 32; j += 8) {
        float v = t[tx][ty + j];   // = W[kb+tx][nb+ty+j]
        __nv_bfloat16 h = __float2bfloat16(v);
        __nv_bfloat16 l = __float2bfloat16(v - __bfloat162float(h));
        size_t o = (size_t)(nb + ty + j) * CC + kb + tx;
        Th[o] = h;
        Tl[o] = l;
    }
}

// ---------------------------------------------------------------------------
// mma.sync bf16 split GEMM: C[M,N] = (Ah+Al)[M,K]*(Bh+Bl)^T[N,K] + bias[N]
// CTA tile 256x128, BK=64 elems (128B rows), NS=2 double buffer.
// 256 threads (8 warps, 4Mx2N, warp tile 64x64). rows padded to 144B.
// Raises FLOP per L2 byte (55.3KB vs 73.7KB per chunk-output) and per ldsm
// wavefront (MMA:ldsm4 ratio 6.0 vs 4.0).
// Triple-segment: grid.x = nseg*NBX; per-block segment select.
// ---------------------------------------------------------------------------
#define NS       2
#define ROWB     144                    // padded row stride (128 B data)
#define A_TILEB  (256 * ROWB)           // 36864
#define B_TILEB  (128 * ROWB)           // 18432
#define STAGEB   (2 * A_TILEB + 2 * B_TILEB)   // 110592
#define GEMM_SMEM (NS * STAGEB)         // 221184
#define NBX      (CC / 128)             // 6 N-tiles per output

struct GemmSeg {
    const __nv_bfloat16 *Ah, *Al, *Bh, *Bl;
    const float* bias;
    float* C;
};

__global__ void __launch_bounds__(256, 1) gemm_bf16s(
    GemmSeg s0_, GemmSeg s1_, GemmSeg s2_)
{
    extern __shared__ char sm_raw[];
    const uint32_t s0 = smem_u32(sm_raw);

    const int tid  = threadIdx.x;
    const int lane = tid & 31;
    const int wid  = tid >> 5;
    const int wm   = wid >> 1;          // 0..3 -> M offset wm*64
    const int wn   = wid & 1;           // 0..1 -> N offset wn*64

    const int bnx = blockIdx.x;
    const int seg = bnx / NBX;
    const int bn  = bnx - seg * NBX;
    const int bm  = blockIdx.y;
    const GemmSeg sg = (seg == 0) ? s0_ : (seg == 1 ? s1_ : s2_);
    const __nv_bfloat16* __restrict__ Ah = sg.Ah;
    const __nv_bfloat16* __restrict__ Al = sg.Al;
    const __nv_bfloat16* __restrict__ Bh = sg.Bh;
    const __nv_bfloat16* __restrict__ Bl = sg.Bl;

    const size_t arow0 = (size_t)bm * 256;
    const size_t brow0 = (size_t)bn * 128;

    // producer mapping: pu = 16B unit within 128B row (0..7), pr = row (0..31)
    const int pu = tid & 7;
    const int pr = tid >> 3;

    float acc[4][8][4];
    #pragma unroll
    for (int mt = 0; mt < 4; mt++)
        #pragma unroll
        for (int nt = 0; nt < 8; nt++)
            #pragma unroll
            for (int e = 0; e < 4; e++) acc[mt][nt][e] = 0.0f;

    auto load_chunk = [&](int c, int buf) {
        const uint32_t stg = s0 + (uint32_t)buf * STAGEB;
        const int k0 = c * 64;
        #pragma unroll
        for (int p = 0; p < 8; p++) {          // A: 256 rows
            int r = pr + p * 32;
            uint32_t d = stg + r * ROWB + pu * 16;
            size_t ga = (arow0 + r) * CC + k0 + pu * 8;
            cp16(d,           Ah + ga);
            cp16(d + A_TILEB, Al + ga);
        }
        #pragma unroll
        for (int p = 0; p < 4; p++) {          // B: 128 rows
            int r = pr + p * 32;
            uint32_t d = stg + 2 * A_TILEB + r * ROWB + pu * 16;
            size_t gb = (brow0 + r) * CC + k0 + pu * 8;
            cp16(d,           Bh + gb);
            cp16(d + B_TILEB, Bl + gb);
        }
        asm volatile("cp.async.commit_group;" ::: "memory");
    };

    load_chunk(0, 0);

    // ldmatrix lane address components (constant across chunks)
    const int a_row = wm * 64 + (lane & 15);
    const int a_k   = (lane >> 4);               // 0/1 -> k-half unit
    const int b_row = wn * 64 + ((lane & 7) | ((lane >> 4) << 3));
    const int b_k   = ((lane >> 3) & 1);

    for (int c = 0; c < 12; c++) {
        if (c + 1 < 12) {
            load_chunk(c + 1, (c + 1) & 1);
            asm volatile("cp.async.wait_group 1;" ::: "memory");
        } else {
            asm volatile("cp.async.wait_group 0;" ::: "memory");
        }
        __syncthreads();

        const uint32_t stg = s0 + (uint32_t)(c & 1) * STAGEB;
        const uint32_t sAh = stg;
        const uint32_t sAl = stg + A_TILEB;
        const uint32_t sBh = stg + 2 * A_TILEB;
        const uint32_t sBl = stg + 2 * A_TILEB + B_TILEB;

        #pragma unroll
        for (int ks = 0; ks < 4; ks++) {
            uint32_t ah[4][4], al[4][4];
            #pragma unroll
            for (int mt = 0; mt < 4; mt++) {
                uint32_t ad = (uint32_t)((a_row + mt * 16) * ROWB +
                                         (ks * 2 + a_k) * 16);
                ldsm4(ah[mt], sAh + ad);
                ldsm4(al[mt], sAl + ad);
            }
            #pragma unroll
            for (int np = 0; np < 4; np++) {
                uint32_t bd = (uint32_t)((b_row + np * 16) * ROWB +
                                         (ks * 2 + b_k) * 16);
                uint32_t rh[4], rl[4];
                ldsm4(rh, sBh + bd);
                ldsm4(rl, sBl + bd);
                #pragma unroll
                for (int mt = 0; mt < 4; mt++) {
                    mma16816(acc[mt][np * 2],     ah[mt], rh);
                    mma16816(acc[mt][np * 2],     ah[mt], rl);
                    mma16816(acc[mt][np * 2],     al[mt], rh);
                    mma16816(acc[mt][np * 2 + 1], ah[mt], rh + 2);
                    mma16816(acc[mt][np * 2 + 1], ah[mt], rl + 2);
                    mma16816(acc[mt][np * 2 + 1], al[mt], rh + 2);
                }
            }
        }
        __syncthreads();
    }

    // epilogue
    const float* bp = sg.bias + bn * 128;
    float* __restrict__ C = sg.C;
    #pragma unroll
    for (int mt = 0; mt < 4; mt++) {
        int row0 = bm * 256 + wm * 64 + mt * 16 + (lane >> 2);
        #pragma unroll
        for (int nt = 0; nt < 8; nt++) {
            int col = wn * 64 + nt * 8 + (lane & 3) * 2;
            float b0 = bp[col], b1 = bp[col + 1];
            float2 v0 = make_float2(acc[mt][nt][0] + b0, acc[mt][nt][1] + b1);
            float2 v1 = make_float2(acc[mt][nt][2] + b0, acc[mt][nt][3] + b1);
            *(float2*)(C + (size_t)row0 * CC + bn * 128 + col) = v0;
            *(float2*)(C + (size_t)(row0 + 8) * CC + bn * 128 + col) = v1;
        }
    }
}

// ---------------------------------------------------------------------------
// Axial attention: one CTA per (axis, b, fixed, head). seq=64, d=64.
// Register softmax (16-lane shfl groups); P reuses the Q smem buffer.
// ---------------------------------------------------------------------------
#define ATTN_SMEM ((4096 + 4160 + 4096) * 4)   // Qs/P, Ks(65-pad), Vs

__global__ void __launch_bounds__(256) attn_kernel()
{
    extern __shared__ float smem[];
    float* Qs = smem;                 // [64][64], reused for P
    float* Ks = Qs + 4096;            // [64][65] padded
    float* Vs = Ks + 4160;            // [64][64]

    const int tid = threadIdx.x;
    int idx = blockIdx.x;
    const int axis = idx / (BB * WW * GRP);
    idx -= axis * (BB * WW * GRP);
    const int b     = idx / (WW * GRP);
    int rem         = idx - b * (WW * GRP);
    const int fixed = rem / GRP;
    const int n     = rem - fixed * GRP;

    size_t base;
    int stride;
    if (axis == 0) {
        base   = ((size_t)b * HH * WW + fixed) * CC + n * 64;
        stride = WW * CC;
    } else {
        base   = ((size_t)(b * HH + fixed)) * (size_t)(WW * CC) + (n + GRP) * 64;
        stride = CC;
    }

    // float4 loads: 1024 units of 16B
    for (int t = tid; t < 1024; t += 256) {
        int i = t >> 4, d = (t & 15) * 4;
        size_t off = base + (size_t)i * stride + d;
        float4 q4 = *(const float4*)(g_q + off);
        float4 k4 = *(const float4*)(g_k + off);
        float4 v4 = *(const float4*)(g_v + off);
        *(float4*)(Qs + i * 64 + d) = q4;
        Ks[i * 65 + d + 0] = k4.x; Ks[i * 65 + d + 1] = k4.y;
        Ks[i * 65 + d + 2] = k4.z; Ks[i * 65 + d + 3] = k4.w;
        *(float4*)(Vs + i * 64 + d) = v4;
    }
    __syncthreads();

    const int tx = tid & 15;
    const int ty = tid >> 4;
    const int i0 = ty * 4;
    const int j0 = tx * 4;

    // S tile in registers
    float acc[4][4];
    #pragma unroll
    for (int a = 0; a < 4; a++)
        #pragma unroll
        for (int c = 0; c < 4; c++) acc[a][c] = 0.0f;
    #pragma unroll 4
    for (int d = 0; d < 64; d++) {
        float qr[4], kr[4];
        #pragma unroll
        for (int a = 0; a < 4; a++) qr[a] = Qs[(i0 + a) * 64 + d];
        #pragma unroll
        for (int c = 0; c < 4; c++) kr[c] = Ks[(j0 + c) * 65 + d];
        #pragma unroll
        for (int a = 0; a < 4; a++)
            #pragma unroll
            for (int c = 0; c < 4; c++)
                acc[a][c] = fmaf(qr[a], kr[c], acc[a][c]);
    }

    // register softmax per row (16-lane groups)
    #pragma unroll
    for (int a = 0; a < 4; a++) {
        float m = fmaxf(fmaxf(acc[a][0], acc[a][1]), fmaxf(acc[a][2], acc[a][3]));
        #pragma unroll
        for (int o = 8; o > 0; o >>= 1)
            m = fmaxf(m, __shfl_xor_sync(0xffffffffu, m, o));
        float e0 = __expf((acc[a][0] - m) * INV_SCALE);
        float e1 = __expf((acc[a][1] - m) * INV_SCALE);
        float e2 = __expf((acc[a][2] - m) * INV_SCALE);
        float e3 = __expf((acc[a][3] - m) * INV_SCALE);
        float s = e0 + e1 + e2 + e3;
        #pragma unroll
        for (int o = 8; o > 0; o >>= 1)
            s += __shfl_xor_sync(0xffffffffu, s, o);
        float inv = 1.0f / s;
        acc[a][0] = e0 * inv; acc[a][1] = e1 * inv;
        acc[a][2] = e2 * inv; acc[a][3] = e3 * inv;
    }

    __syncthreads();   // all Qs/Ks reads done -> safe to overwrite Qs with P
    #pragma unroll
    for (int a = 0; a < 4; a++)
        *(float4*)(Qs + (i0 + a) * 64 + j0) =
            make_float4(acc[a][0], acc[a][1], acc[a][2], acc[a][3]);
    __syncthreads();

    // O = P V
    {
        float o_[4][4];
        #pragma unroll
        for (int a = 0; a < 4; a++)
            #pragma unroll
            for (int c = 0; c < 4; c++) o_[a][c] = 0.0f;
        #pragma unroll 4
        for (int j = 0; j < 64; j++) {
            float pr[4], vr[4];
            #pragma unroll
            for (int a = 0; a < 4; a++) pr[a] = Qs[(i0 + a) * 64 + j];
            #pragma unroll
            for (int c = 0; c < 4; c++) vr[c] = Vs[j * 64 + j0 + c];
            #pragma unroll
            for (int a = 0; a < 4; a++)
                #pragma unroll
                for (int c = 0; c < 4; c++)
                    o_[a][c] = fmaf(pr[a], vr[c], o_[a][c]);
        }
        #pragma unroll
        for (int a = 0; a < 4; a++) {
            size_t off = base + (size_t)(i0 + a) * stride + j0;
            __nv_bfloat16 h[4], l[4];
            #pragma unroll
            for (int c = 0; c < 4; c++) {
                h[c] = __float2bfloat16(o_[a][c]);
                l[c] = __float2bfloat16(o_[a][c] - __bfloat162float(h[c]));
            }
            *(uint2*)(g_ah + off) = make_uint2(packbf(h[0], h[1]), packbf(h[2], h[3]));
            *(uint2*)(g_al + off) = make_uint2(packbf(l[0], l[1]), packbf(l[2], l[3]));
        }
    }
}

// ---------------------------------------------------------------------------
extern "C" void kernel_launch(void* const* d_in, const int* in_sizes, int n_in,
                              void* d_out, int out_size)
{
    const float* queries = (const float*)d_in[0];
    const float* values  = (const float*)d_in[1];
    const float* Wq = (const float*)d_in[2];
    const float* bq = (const float*)d_in[3];
    const float* Wk = (const float*)d_in[4];
    const float* bk = (const float*)d_in[5];
    const float* Wv = (const float*)d_in[6];
    const float* bv = (const float*)d_in[7];
    const float* Wo = (const float*)d_in[8];
    const float* bo = (const float*)d_in[9];
    float* out = (float*)d_out;

    float *qp, *kp, *vp;
    __nv_bfloat16 *qh, *ql, *vh, *vl, *ah, *al, *wth, *wtl;
    cudaGetSymbolAddress((void**)&qp, g_q);
    cudaGetSymbolAddress((void**)&kp, g_k);
    cudaGetSymbolAddress((void**)&vp, g_v);
    cudaGetSymbolAddress((void**)&qh, g_qh);
    cudaGetSymbolAddress((void**)&ql, g_ql);
    cudaGetSymbolAddress((void**)&vh, g_vh);
    cudaGetSymbolAddress((void**)&vl, g_vl);
    cudaGetSymbolAddress((void**)&ah, g_ah);
    cudaGetSymbolAddress((void**)&al, g_al);
    cudaGetSymbolAddress((void**)&wth, g_wth);
    cudaGetSymbolAddress((void**)&wtl, g_wtl);

    cudaFuncSetAttribute(attn_kernel, cudaFuncAttributeMaxDynamicSharedMemorySize,
                         ATTN_SMEM);
    cudaFuncSetAttribute(gemm_bf16s, cudaFuncAttributeMaxDynamicSharedMemorySize,
                         GEMM_SMEM);

    const int n4 = MTOT * CC / 4;

    // weight transpose + split (launches 0-3)
    dim3 wtg(CC / 32, CC / 32), wtb(32, 8);
    __nv_bfloat16* WqH = wth + 0 * (size_t)CC * CC; __nv_bfloat16* WqL = wtl + 0 * (size_t)CC * CC;
    __nv_bfloat16* WkH = wth + 1 * (size_t)CC * CC; __nv_bfloat16* WkL = wtl + 1 * (size_t)CC * CC;
    __nv_bfloat16* WvH = wth + 2 * (size_t)CC * CC; __nv_bfloat16* WvL = wtl + 2 * (size_t)CC * CC;
    __nv_bfloat16* WoH = wth + 3 * (size_t)CC * CC; __nv_bfloat16* WoL = wtl + 3 * (size_t)CC * CC;
    wt_split<<<wtg, wtb>>>(Wq, WqH, WqL);
    wt_split<<<wtg, wtb>>>(Wk, WkH, WkL);
    wt_split<<<wtg, wtb>>>(Wv, WvH, WvL);
    wt_split<<<wtg, wtb>>>(Wo, WoH, WoL);

    // input split conversions (both tensors, one launch)
    conv_split2<<<(2 * n4 + 255) / 256, 256>>>(
        (const float4*)queries, (uint2*)qh, (uint2*)ql,
        (const float4*)values,  (uint2*)vh, (uint2*)vl, n4);

    // Q, K, V projections fused into one launch (3 segments)
    GemmSeg sq = {qh, ql, WqH, WqL, bq, qp};
    GemmSeg sk = {vh, vl, WkH, WkL, bk, kp};
    GemmSeg sv = {vh, vl, WvH, WvL, bv, vp};
    dim3 g3(3 * NBX, MTOT / 256);
    gemm_bf16s<<<g3, 256, GEMM_SMEM>>>(sq, sk, sv);

    attn_kernel<<<2 * BB * WW * GRP, 256, ATTN_SMEM>>>();

    // output projection
    GemmSeg so = {ah, al, WoH, WoL, bo, out};
    dim3 g1(NBX, MTOT / 256);
    gemm_bf16s<<<g1, 256, GEMM_SMEM>>>(so, so, so);
}

// round 14
// speedup vs baseline: 1.4379x; 1.2831x over previous
#include <cuda_runtime.h>
#include <cuda_fp16.h>
#include <cstdint>

// Problem constants
#define BB   16
#define HH   64
#define WW   64
#define CC   768
#define GRP  6            // heads per axis group
#define MTOT (BB*HH*WW)   // 65536
#define INV_SCALE 0.125f  // 1/sqrt(64)

// ---------------------------------------------------------------------------
// Static device scratch
// ---------------------------------------------------------------------------
__device__ float g_q[MTOT * CC];
__device__ float g_k[MTOT * CC];
__device__ float g_v[MTOT * CC];
__device__ __half g_qh[MTOT * CC];   // queries hi
__device__ __half g_ql[MTOT * CC];   // queries lo
__device__ __half g_vh[MTOT * CC];   // values hi
__device__ __half g_vl[MTOT * CC];   // values lo
__device__ __half g_ah[MTOT * CC];   // attn out hi
__device__ __half g_al[MTOT * CC];   // attn out lo
// transposed fp16 weights: [4][N=768][K=768], order q,k,v,o (single plane)
__device__ __half g_wt[4][CC * CC];

// ---------------------------------------------------------------------------
// helpers
// ---------------------------------------------------------------------------
__device__ __forceinline__ uint32_t smem_u32(const void* p) {
    uint32_t a;
    asm("{ .reg .u64 t; cvta.to.shared.u64 t, %1; cvt.u32.u64 %0, t; }"
        : "=r"(a) : "l"(p));
    return a;
}
__device__ __forceinline__ uint32_t packh(__half a, __half b) {
    return (uint32_t)__half_as_ushort(a) |
           ((uint32_t)__half_as_ushort(b) << 16);
}
__device__ __forceinline__ void cp16(uint32_t dst, const void* src) {
    asm volatile("cp.async.cg.shared.global [%0], [%1], 16;"
                 :: "r"(dst), "l"(src) : "memory");
}
__device__ __forceinline__ void ldsm4(uint32_t* r, uint32_t addr) {
    asm volatile("ldmatrix.sync.aligned.m8n8.x4.shared.b16 {%0,%1,%2,%3}, [%4];"
                 : "=r"(r[0]), "=r"(r[1]), "=r"(r[2]), "=r"(r[3]) : "r"(addr));
}
__device__ __forceinline__ void mma16816(float* d, const uint32_t* a,
                                         const uint32_t* b) {
    asm volatile(
        "mma.sync.aligned.m16n8k16.row.col.f32.f16.f16.f32 "
        "{%0,%1,%2,%3}, {%4,%5,%6,%7}, {%8,%9}, {%0,%1,%2,%3};"
        : "+f"(d[0]), "+f"(d[1]), "+f"(d[2]), "+f"(d[3])
        : "r"(a[0]), "r"(a[1]), "r"(a[2]), "r"(a[3]), "r"(b[0]), "r"(b[1]));
}

// ---------------------------------------------------------------------------
// Split conversion: fp32 -> fp16 hi + fp16 lo. Dual-source single launch.
// ---------------------------------------------------------------------------
__global__ void conv_split2(const float4* __restrict__ x0, uint2* __restrict__ h0,
                            uint2* __restrict__ l0,
                            const float4* __restrict__ x1, uint2* __restrict__ h1,
                            uint2* __restrict__ l1, int n4) {
    int i = blockIdx.x * blockDim.x + threadIdx.x;
    const float4* x; uint2 *h, *l;
    if (i >= n4) {
        i -= n4;
        if (i >= n4) return;
        x = x1; h = h1; l = l1;
    } else { x = x0; h = h0; l = l0; }
    float4 v = x[i];
    __half h0_ = __float2half_rn(v.x), h1_ = __float2half_rn(v.y);
    __half h2_ = __float2half_rn(v.z), h3_ = __float2half_rn(v.w);
    __half l0_ = __float2half_rn(v.x - __half2float(h0_));
    __half l1_ = __float2half_rn(v.y - __half2float(h1_));
    __half l2_ = __float2half_rn(v.z - __half2float(h2_));
    __half l3_ = __float2half_rn(v.w - __half2float(h3_));
    h[i] = make_uint2(packh(h0_, h1_), packh(h2_, h3_));
    l[i] = make_uint2(packh(l0_, l1_), packh(l2_, l3_));
}

// ---------------------------------------------------------------------------
// Weight transpose: W[K=768][N=768] -> T [N=768][K=768] fp16 (single plane)
// ---------------------------------------------------------------------------
__global__ void wt_conv(const float* __restrict__ W, __half* __restrict__ T) {
    __shared__ float t[32][33];
    int nb = blockIdx.x * 32, kb = blockIdx.y * 32;
    int tx = threadIdx.x, ty = threadIdx.y;
    #pragma unroll
    for (int j = 0; j < 32; j += 8)
        t[ty + j][tx] = W[(size_t)(kb + ty + j) * CC + nb + tx];
    __syncthreads();
    #pragma unroll
    for (int j = 0; j < 32; j += 8) {
        float v = t[tx][ty + j];   // = W[kb+tx][nb+ty+j]
        T[(size_t)(nb + ty + j) * CC + kb + tx] = __float2half_rn(v);
    }
}

// ---------------------------------------------------------------------------
// mma.sync fp16 2-product GEMM: C[M,N] = (Ah+Al)[M,K]*Bh^T[N,K] + bias[N]
// A split fp16 hi/lo (22-bit effective), B single fp16 (11-bit).
// CTA tile 256x128, BK=64 elems (128B rows), NS=2 double buffer.
// 256 threads (8 warps, 4Mx2N, warp tile 64x64). rows padded to 144B.
// Triple-segment: grid.x = nseg*NBX; per-block segment select.
// ---------------------------------------------------------------------------
#define NS       2
#define ROWB     144                    // padded row stride (128 B data)
#define A_TILEB  (256 * ROWB)           // 36864
#define B_TILEB  (128 * ROWB)           // 18432
#define STAGEB   (2 * A_TILEB + B_TILEB)       // 92160
#define GEMM_SMEM (NS * STAGEB)         // 184320
#define NBX      (CC / 128)             // 6 N-tiles per output

struct GemmSeg {
    const __half *Ah, *Al, *Bh;
    const float* bias;
    float* C;
};

__global__ void __launch_bounds__(256, 1) gemm_f16s(
    GemmSeg s0_, GemmSeg s1_, GemmSeg s2_)
{
    extern __shared__ char sm_raw[];
    const uint32_t s0 = smem_u32(sm_raw);

    const int tid  = threadIdx.x;
    const int lane = tid & 31;
    const int wid  = tid >> 5;
    const int wm   = wid >> 1;          // 0..3 -> M offset wm*64
    const int wn   = wid & 1;           // 0..1 -> N offset wn*64

    const int bnx = blockIdx.x;
    const int seg = bnx / NBX;
    const int bn  = bnx - seg * NBX;
    const int bm  = blockIdx.y;
    const GemmSeg sg = (seg == 0) ? s0_ : (seg == 1 ? s1_ : s2_);
    const __half* __restrict__ Ah = sg.Ah;
    const __half* __restrict__ Al = sg.Al;
    const __half* __restrict__ Bh = sg.Bh;

    const size_t arow0 = (size_t)bm * 256;
    const size_t brow0 = (size_t)bn * 128;

    // producer mapping: pu = 16B unit within 128B row (0..7), pr = row (0..31)
    const int pu = tid & 7;
    const int pr = tid >> 3;

    float acc[4][8][4];
    #pragma unroll
    for (int mt = 0; mt < 4; mt++)
        #pragma unroll
        for (int nt = 0; nt < 8; nt++)
            #pragma unroll
            for (int e = 0; e < 4; e++) acc[mt][nt][e] = 0.0f;

    auto load_chunk = [&](int c, int buf) {
        const uint32_t stg = s0 + (uint32_t)buf * STAGEB;
        const int k0 = c * 64;
        #pragma unroll
        for (int p = 0; p < 8; p++) {          // A: 256 rows, hi + lo
            int r = pr + p * 32;
            uint32_t d = stg + r * ROWB + pu * 16;
            size_t ga = (arow0 + r) * CC + k0 + pu * 8;
            cp16(d,           Ah + ga);
            cp16(d + A_TILEB, Al + ga);
        }
        #pragma unroll
        for (int p = 0; p < 4; p++) {          // B: 128 rows, hi only
            int r = pr + p * 32;
            uint32_t d = stg + 2 * A_TILEB + r * ROWB + pu * 16;
            size_t gb = (brow0 + r) * CC + k0 + pu * 8;
            cp16(d, Bh + gb);
        }
        asm volatile("cp.async.commit_group;" ::: "memory");
    };

    load_chunk(0, 0);

    // ldmatrix lane address components (constant across chunks)
    const int a_row = wm * 64 + (lane & 15);
    const int a_k   = (lane >> 4);               // 0/1 -> k-half unit
    const int b_row = wn * 64 + ((lane & 7) | ((lane >> 4) << 3));
    const int b_k   = ((lane >> 3) & 1);

    for (int c = 0; c < 12; c++) {
        if (c + 1 < 12) {
            load_chunk(c + 1, (c + 1) & 1);
            asm volatile("cp.async.wait_group 1;" ::: "memory");
        } else {
            asm volatile("cp.async.wait_group 0;" ::: "memory");
        }
        __syncthreads();

        const uint32_t stg = s0 + (uint32_t)(c & 1) * STAGEB;
        const uint32_t sAh = stg;
        const uint32_t sAl = stg + A_TILEB;
        const uint32_t sBh = stg + 2 * A_TILEB;

        #pragma unroll
        for (int ks = 0; ks < 4; ks++) {
            uint32_t ah[4][4], al[4][4];
            #pragma unroll
            for (int mt = 0; mt < 4; mt++) {
                uint32_t ad = (uint32_t)((a_row + mt * 16) * ROWB +
                                         (ks * 2 + a_k) * 16);
                ldsm4(ah[mt], sAh + ad);
                ldsm4(al[mt], sAl + ad);
            }
            #pragma unroll
            for (int np = 0; np < 4; np++) {
                uint32_t bd = (uint32_t)((b_row + np * 16) * ROWB +
                                         (ks * 2 + b_k) * 16);
                uint32_t rh[4];
                ldsm4(rh, sBh + bd);
                #pragma unroll
                for (int mt = 0; mt < 4; mt++) {
                    mma16816(acc[mt][np * 2],     ah[mt], rh);
                    mma16816(acc[mt][np * 2],     al[mt], rh);
                    mma16816(acc[mt][np * 2 + 1], ah[mt], rh + 2);
                    mma16816(acc[mt][np * 2 + 1], al[mt], rh + 2);
                }
            }
        }
        __syncthreads();
    }

    // epilogue
    const float* bp = sg.bias + bn * 128;
    float* __restrict__ C = sg.C;
    #pragma unroll
    for (int mt = 0; mt < 4; mt++) {
        int row0 = bm * 256 + wm * 64 + mt * 16 + (lane >> 2);
        #pragma unroll
        for (int nt = 0; nt < 8; nt++) {
            int col = wn * 64 + nt * 8 + (lane & 3) * 2;
            float b0 = bp[col], b1 = bp[col + 1];
            float2 v0 = make_float2(acc[mt][nt][0] + b0, acc[mt][nt][1] + b1);
            float2 v1 = make_float2(acc[mt][nt][2] + b0, acc[mt][nt][3] + b1);
            *(float2*)(C + (size_t)row0 * CC + bn * 128 + col) = v0;
            *(float2*)(C + (size_t)(row0 + 8) * CC + bn * 128 + col) = v1;
        }
    }
}

// ---------------------------------------------------------------------------
// Axial attention: one CTA per (axis, b, fixed, head). seq=64, d=64.
// Register softmax (16-lane shfl groups); P reuses the Q smem buffer.
// Writes fp16 hi/lo attention output for the final GEMM.
// ---------------------------------------------------------------------------
#define ATTN_SMEM ((4096 + 4160 + 4096) * 4)   // Qs/P, Ks(65-pad), Vs

__global__ void __launch_bounds__(256) attn_kernel()
{
    extern __shared__ float smem[];
    float* Qs = smem;                 // [64][64], reused for P
    float* Ks = Qs + 4096;            // [64][65] padded
    float* Vs = Ks + 4160;            // [64][64]

    const int tid = threadIdx.x;
    int idx = blockIdx.x;
    const int axis = idx / (BB * WW * GRP);
    idx -= axis * (BB * WW * GRP);
    const int b     = idx / (WW * GRP);
    int rem         = idx - b * (WW * GRP);
    const int fixed = rem / GRP;
    const int n     = rem - fixed * GRP;

    size_t base;
    int stride;
    if (axis == 0) {
        base   = ((size_t)b * HH * WW + fixed) * CC + n * 64;
        stride = WW * CC;
    } else {
        base   = ((size_t)(b * HH + fixed)) * (size_t)(WW * CC) + (n + GRP) * 64;
        stride = CC;
    }

    // float4 loads: 1024 units of 16B
    for (int t = tid; t < 1024; t += 256) {
        int i = t >> 4, d = (t & 15) * 4;
        size_t off = base + (size_t)i * stride + d;
        float4 q4 = *(const float4*)(g_q + off);
        float4 k4 = *(const float4*)(g_k + off);
        float4 v4 = *(const float4*)(g_v + off);
        *(float4*)(Qs + i * 64 + d) = q4;
        Ks[i * 65 + d + 0] = k4.x; Ks[i * 65 + d + 1] = k4.y;
        Ks[i * 65 + d + 2] = k4.z; Ks[i * 65 + d + 3] = k4.w;
        *(float4*)(Vs + i * 64 + d) = v4;
    }
    __syncthreads();

    const int tx = tid & 15;
    const int ty = tid >> 4;
    const int i0 = ty * 4;
    const int j0 = tx * 4;

    // S tile in registers
    float acc[4][4];
    #pragma unroll
    for (int a = 0; a < 4; a++)
        #pragma unroll
        for (int c = 0; c < 4; c++) acc[a][c] = 0.0f;
    #pragma unroll 4
    for (int d = 0; d < 64; d++) {
        float qr[4], kr[4];
        #pragma unroll
        for (int a = 0; a < 4; a++) qr[a] = Qs[(i0 + a) * 64 + d];
        #pragma unroll
        for (int c = 0; c < 4; c++) kr[c] = Ks[(j0 + c) * 65 + d];
        #pragma unroll
        for (int a = 0; a < 4; a++)
            #pragma unroll
            for (int c = 0; c < 4; c++)
                acc[a][c] = fmaf(qr[a], kr[c], acc[a][c]);
    }

    // register softmax per row (16-lane groups)
    #pragma unroll
    for (int a = 0; a < 4; a++) {
        float m = fmaxf(fmaxf(acc[a][0], acc[a][1]), fmaxf(acc[a][2], acc[a][3]));
        #pragma unroll
        for (int o = 8; o > 0; o >>= 1)
            m = fmaxf(m, __shfl_xor_sync(0xffffffffu, m, o));
        float e0 = __expf((acc[a][0] - m) * INV_SCALE);
        float e1 = __expf((acc[a][1] - m) * INV_SCALE);
        float e2 = __expf((acc[a][2] - m) * INV_SCALE);
        float e3 = __expf((acc[a][3] - m) * INV_SCALE);
        float s = e0 + e1 + e2 + e3;
        #pragma unroll
        for (int o = 8; o > 0; o >>= 1)
            s += __shfl_xor_sync(0xffffffffu, s, o);
        float inv = 1.0f / s;
        acc[a][0] = e0 * inv; acc[a][1] = e1 * inv;
        acc[a][2] = e2 * inv; acc[a][3] = e3 * inv;
    }

    __syncthreads();   // all Qs/Ks reads done -> safe to overwrite Qs with P
    #pragma unroll
    for (int a = 0; a < 4; a++)
        *(float4*)(Qs + (i0 + a) * 64 + j0) =
            make_float4(acc[a][0], acc[a][1], acc[a][2], acc[a][3]);
    __syncthreads();

    // O = P V
    {
        float o_[4][4];
        #pragma unroll
        for (int a = 0; a < 4; a++)
            #pragma unroll
            for (int c = 0; c < 4; c++) o_[a][c] = 0.0f;
        #pragma unroll 4
        for (int j = 0; j < 64; j++) {
            float pr[4], vr[4];
            #pragma unroll
            for (int a = 0; a < 4; a++) pr[a] = Qs[(i0 + a) * 64 + j];
            #pragma unroll
            for (int c = 0; c < 4; c++) vr[c] = Vs[j * 64 + j0 + c];
            #pragma unroll
            for (int a = 0; a < 4; a++)
                #pragma unroll
                for (int c = 0; c < 4; c++)
                    o_[a][c] = fmaf(pr[a], vr[c], o_[a][c]);
        }
        #pragma unroll
        for (int a = 0; a < 4; a++) {
            size_t off = base + (size_t)(i0 + a) * stride + j0;
            __half h[4], l[4];
            #pragma unroll
            for (int c = 0; c < 4; c++) {
                h[c] = __float2half_rn(o_[a][c]);
                l[c] = __float2half_rn(o_[a][c] - __half2float(h[c]));
            }
            *(uint2*)(g_ah + off) = make_uint2(packh(h[0], h[1]), packh(h[2], h[3]));
            *(uint2*)(g_al + off) = make_uint2(packh(l[0], l[1]), packh(l[2], l[3]));
        }
    }
}

// ---------------------------------------------------------------------------
extern "C" void kernel_launch(void* const* d_in, const int* in_sizes, int n_in,
                              void* d_out, int out_size)
{
    const float* queries = (const float*)d_in[0];
    const float* values  = (const float*)d_in[1];
    const float* Wq = (const float*)d_in[2];
    const float* bq = (const float*)d_in[3];
    const float* Wk = (const float*)d_in[4];
    const float* bk = (const float*)d_in[5];
    const float* Wv = (const float*)d_in[6];
    const float* bv = (const float*)d_in[7];
    const float* Wo = (const float*)d_in[8];
    const float* bo = (const float*)d_in[9];
    float* out = (float*)d_out;

    float *qp, *kp, *vp;
    __half *qh, *ql, *vh, *vl, *ah, *al, *wt;
    cudaGetSymbolAddress((void**)&qp, g_q);
    cudaGetSymbolAddress((void**)&kp, g_k);
    cudaGetSymbolAddress((void**)&vp, g_v);
    cudaGetSymbolAddress((void**)&qh, g_qh);
    cudaGetSymbolAddress((void**)&ql, g_ql);
    cudaGetSymbolAddress((void**)&vh, g_vh);
    cudaGetSymbolAddress((void**)&vl, g_vl);
    cudaGetSymbolAddress((void**)&ah, g_ah);
    cudaGetSymbolAddress((void**)&al, g_al);
    cudaGetSymbolAddress((void**)&wt, g_wt);

    cudaFuncSetAttribute(attn_kernel, cudaFuncAttributeMaxDynamicSharedMemorySize,
                         ATTN_SMEM);
    cudaFuncSetAttribute(gemm_f16s, cudaFuncAttributeMaxDynamicSharedMemorySize,
                         GEMM_SMEM);

    const int n4 = MTOT * CC / 4;

    // weight transpose + fp16 (launches 0-3)
    dim3 wtg(CC / 32, CC / 32), wtb(32, 8);
    __half* WqT = wt + 0 * (size_t)CC * CC;
    __half* WkT = wt + 1 * (size_t)CC * CC;
    __half* WvT = wt + 2 * (size_t)CC * CC;
    __half* WoT = wt + 3 * (size_t)CC * CC;
    wt_conv<<<wtg, wtb>>>(Wq, WqT);
    wt_conv<<<wtg, wtb>>>(Wk, WkT);
    wt_conv<<<wtg, wtb>>>(Wv, WvT);
    wt_conv<<<wtg, wtb>>>(Wo, WoT);

    // input split conversions (both tensors, one launch)
    conv_split2<<<(2 * n4 + 255) / 256, 256>>>(
        (const float4*)queries, (uint2*)qh, (uint2*)ql,
        (const float4*)values,  (uint2*)vh, (uint2*)vl, n4);

    // Q, K, V projections fused into one launch (3 segments)
    GemmSeg sq = {qh, ql, WqT, bq, qp};
    GemmSeg sk = {vh, vl, WkT, bk, kp};
    GemmSeg sv = {vh, vl, WvT, bv, vp};
    dim3 g3(3 * NBX, MTOT / 256);
    gemm_f16s<<<g3, 256, GEMM_SMEM>>>(sq, sk, sv);

    attn_kernel<<<2 * BB * WW * GRP, 256, ATTN_SMEM>>>();

    // output projection
    GemmSeg so = {ah, al, WoT, bo, out};
    dim3 g1(NBX, MTOT / 256);
    gemm_f16s<<<g1, 256, GEMM_SMEM>>>(so, so, so);
}

// round 17
// speedup vs baseline: 1.5016x; 1.0443x over previous
#include <cuda_runtime.h>
#include <cuda_fp16.h>
#include <cstdint>

// Problem constants
#define BB   16
#define HH   64
#define WW   64
#define CC   768
#define GRP  6            // heads per axis group
#define MTOT (BB*HH*WW)   // 65536
#define INV_SCALE 0.125f  // 1/sqrt(64)

// ---------------------------------------------------------------------------
// Static device scratch
// ---------------------------------------------------------------------------
__device__ float g_q[MTOT * CC];
__device__ float g_k[MTOT * CC];
__device__ float g_v[MTOT * CC];
__device__ __half g_qh[MTOT * CC];   // queries hi
__device__ __half g_ql[MTOT * CC];   // queries lo
__device__ __half g_vh[MTOT * CC];   // values hi
__device__ __half g_vl[MTOT * CC];   // values lo
__device__ __half g_ah[MTOT * CC];   // attn out hi
__device__ __half g_al[MTOT * CC];   // attn out lo
// transposed fp16 weights: [4][N=768][K=768], order q,k,v,o (single plane)
__device__ __half g_wt[4][CC * CC];

// ---------------------------------------------------------------------------
// helpers
// ---------------------------------------------------------------------------
__device__ __forceinline__ uint32_t smem_u32(const void* p) {
    uint32_t a;
    asm("{ .reg .u64 t; cvta.to.shared.u64 t, %1; cvt.u32.u64 %0, t; }"
        : "=r"(a) : "l"(p));
    return a;
}
__device__ __forceinline__ uint32_t packh(__half a, __half b) {
    return (uint32_t)__half_as_ushort(a) |
           ((uint32_t)__half_as_ushort(b) << 16);
}
__device__ __forceinline__ void cp16(uint32_t dst, const void* src) {
    asm volatile("cp.async.cg.shared.global [%0], [%1], 16;"
                 :: "r"(dst), "l"(src) : "memory");
}
__device__ __forceinline__ void ldsm4(uint32_t* r, uint32_t addr) {
    asm volatile("ldmatrix.sync.aligned.m8n8.x4.shared.b16 {%0,%1,%2,%3}, [%4];"
                 : "=r"(r[0]), "=r"(r[1]), "=r"(r[2]), "=r"(r[3]) : "r"(addr));
}
__device__ __forceinline__ void mma16816(float* d, const uint32_t* a,
                                         const uint32_t* b) {
    asm volatile(
        "mma.sync.aligned.m16n8k16.row.col.f32.f16.f16.f32 "
        "{%0,%1,%2,%3}, {%4,%5,%6,%7}, {%8,%9}, {%0,%1,%2,%3};"
        : "+f"(d[0]), "+f"(d[1]), "+f"(d[2]), "+f"(d[3])
        : "r"(a[0]), "r"(a[1]), "r"(a[2]), "r"(a[3]), "r"(b[0]), "r"(b[1]));
}

// ---------------------------------------------------------------------------
// Split conversion: fp32 -> fp16 hi + fp16 lo. Dual-source single launch.
// ---------------------------------------------------------------------------
__global__ void conv_split2(const float4* __restrict__ x0, uint2* __restrict__ h0,
                            uint2* __restrict__ l0,
                            const float4* __restrict__ x1, uint2* __restrict__ h1,
                            uint2* __restrict__ l1, int n4) {
    int i = blockIdx.x * blockDim.x + threadIdx.x;
    const float4* x; uint2 *h, *l;
    if (i >= n4) {
        i -= n4;
        if (i >= n4) return;
        x = x1; h = h1; l = l1;
    } else { x = x0; h = h0; l = l0; }
    float4 v = x[i];
    __half h0_ = __float2half_rn(v.x), h1_ = __float2half_rn(v.y);
    __half h2_ = __float2half_rn(v.z), h3_ = __float2half_rn(v.w);
    __half l0_ = __float2half_rn(v.x - __half2float(h0_));
    __half l1_ = __float2half_rn(v.y - __half2float(h1_));
    __half l2_ = __float2half_rn(v.z - __half2float(h2_));
    __half l3_ = __float2half_rn(v.w - __half2float(h3_));
    h[i] = make_uint2(packh(h0_, h1_), packh(h2_, h3_));
    l[i] = make_uint2(packh(l0_, l1_), packh(l2_, l3_));
}

// ---------------------------------------------------------------------------
// Weight transpose: W[K=768][N=768] -> T [N=768][K=768] fp16 (single plane)
// ---------------------------------------------------------------------------
__global__ void wt_conv(const float* __restrict__ W, __half* __restrict__ T) {
    __shared__ float t[32][33];
    int nb = blockIdx.x * 32, kb = blockIdx.y * 32;
    int tx = threadIdx.x, ty = threadIdx.y;
    #pragma unroll
    for (int j = 0; j < 32; j += 8)
        t[ty + j][tx] = W[(size_t)(kb + ty + j) * CC + nb + tx];
    __syncthreads();
    #pragma unroll
    for (int j = 0; j < 32; j += 8) {
        float v = t[tx][ty + j];   // = W[kb+tx][nb+ty+j]
        T[(size_t)(nb + ty + j) * CC + kb + tx] = __float2half_rn(v);
    }
}

// ---------------------------------------------------------------------------
// mma.sync fp16 2-product GEMM: C[M,N] = (Ah+Al)[M,K]*Bh^T[N,K] + bias[N]
// CTA tile 256x128, BK=64 elems (128B rows), NS=2 double buffer.
// 256 threads (8 warps, 4Mx2N, warp tile 64x64). rows padded to 144B.
// ---------------------------------------------------------------------------
#define NS       2
#define ROWB     144                    // padded row stride (128 B data)
#define A_TILEB  (256 * ROWB)           // 36864
#define B_TILEB  (128 * ROWB)           // 18432
#define STAGEB   (2 * A_TILEB + B_TILEB)       // 92160
#define GEMM_SMEM (NS * STAGEB)         // 184320
#define NBX      (CC / 128)             // 6 N-tiles per output

struct GemmSeg {
    const __half *Ah, *Al, *Bh;
    const float* bias;
    float* C;
};

__global__ void __launch_bounds__(256, 1) gemm_f16s(
    GemmSeg s0_, GemmSeg s1_, GemmSeg s2_)
{
    extern __shared__ char sm_raw[];
    const uint32_t s0 = smem_u32(sm_raw);

    const int tid  = threadIdx.x;
    const int lane = tid & 31;
    const int wid  = tid >> 5;
    const int wm   = wid >> 1;          // 0..3 -> M offset wm*64
    const int wn   = wid & 1;           // 0..1 -> N offset wn*64

    const int bnx = blockIdx.x;
    const int seg = bnx / NBX;
    const int bn  = bnx - seg * NBX;
    const int bm  = blockIdx.y;
    const GemmSeg sg = (seg == 0) ? s0_ : (seg == 1 ? s1_ : s2_);
    const __half* __restrict__ Ah = sg.Ah;
    const __half* __restrict__ Al = sg.Al;
    const __half* __restrict__ Bh = sg.Bh;

    const size_t arow0 = (size_t)bm * 256;
    const size_t brow0 = (size_t)bn * 128;

    const int pu = tid & 7;
    const int pr = tid >> 3;

    float acc[4][8][4];
    #pragma unroll
    for (int mt = 0; mt < 4; mt++)
        #pragma unroll
        for (int nt = 0; nt < 8; nt++)
            #pragma unroll
            for (int e = 0; e < 4; e++) acc[mt][nt][e] = 0.0f;

    auto load_chunk = [&](int c, int buf) {
        const uint32_t stg = s0 + (uint32_t)buf * STAGEB;
        const int k0 = c * 64;
        #pragma unroll
        for (int p = 0; p < 8; p++) {          // A: 256 rows, hi + lo
            int r = pr + p * 32;
            uint32_t d = stg + r * ROWB + pu * 16;
            size_t ga = (arow0 + r) * CC + k0 + pu * 8;
            cp16(d,           Ah + ga);
            cp16(d + A_TILEB, Al + ga);
        }
        #pragma unroll
        for (int p = 0; p < 4; p++) {          // B: 128 rows, hi only
            int r = pr + p * 32;
            uint32_t d = stg + 2 * A_TILEB + r * ROWB + pu * 16;
            size_t gb = (brow0 + r) * CC + k0 + pu * 8;
            cp16(d, Bh + gb);
        }
        asm volatile("cp.async.commit_group;" ::: "memory");
    };

    load_chunk(0, 0);

    const int a_row = wm * 64 + (lane & 15);
    const int a_k   = (lane >> 4);
    const int b_row = wn * 64 + ((lane & 7) | ((lane >> 4) << 3));
    const int b_k   = ((lane >> 3) & 1);

    for (int c = 0; c < 12; c++) {
        if (c + 1 < 12) {
            load_chunk(c + 1, (c + 1) & 1);
            asm volatile("cp.async.wait_group 1;" ::: "memory");
        } else {
            asm volatile("cp.async.wait_group 0;" ::: "memory");
        }
        __syncthreads();

        const uint32_t stg = s0 + (uint32_t)(c & 1) * STAGEB;
        const uint32_t sAh = stg;
        const uint32_t sAl = stg + A_TILEB;
        const uint32_t sBh = stg + 2 * A_TILEB;

        #pragma unroll
        for (int ks = 0; ks < 4; ks++) {
            uint32_t ah[4][4], al[4][4];
            #pragma unroll
            for (int mt = 0; mt < 4; mt++) {
                uint32_t ad = (uint32_t)((a_row + mt * 16) * ROWB +
                                         (ks * 2 + a_k) * 16);
                ldsm4(ah[mt], sAh + ad);
                ldsm4(al[mt], sAl + ad);
            }
            #pragma unroll
            for (int np = 0; np < 4; np++) {
                uint32_t bd = (uint32_t)((b_row + np * 16) * ROWB +
                                         (ks * 2 + b_k) * 16);
                uint32_t rh[4];
                ldsm4(rh, sBh + bd);
                #pragma unroll
                for (int mt = 0; mt < 4; mt++) {
                    mma16816(acc[mt][np * 2],     ah[mt], rh);
                    mma16816(acc[mt][np * 2],     al[mt], rh);
                    mma16816(acc[mt][np * 2 + 1], ah[mt], rh + 2);
                    mma16816(acc[mt][np * 2 + 1], al[mt], rh + 2);
                }
            }
        }
        __syncthreads();
    }

    const float* bp = sg.bias + bn * 128;
    float* __restrict__ C = sg.C;
    #pragma unroll
    for (int mt = 0; mt < 4; mt++) {
        int row0 = bm * 256 + wm * 64 + mt * 16 + (lane >> 2);
        #pragma unroll
        for (int nt = 0; nt < 8; nt++) {
            int col = wn * 64 + nt * 8 + (lane & 3) * 2;
            float b0 = bp[col], b1 = bp[col + 1];
            float2 v0 = make_float2(acc[mt][nt][0] + b0, acc[mt][nt][1] + b1);
            float2 v1 = make_float2(acc[mt][nt][2] + b0, acc[mt][nt][3] + b1);
            *(float2*)(C + (size_t)row0 * CC + bn * 128 + col) = v0;
            *(float2*)(C + (size_t)(row0 + 8) * CC + bn * 128 + col) = v1;
        }
    }
}

// ---------------------------------------------------------------------------
// Tensor-core axial attention: one CTA (128 thr, 4 warps) per
// (axis, b, fixed, head). seq=64, d=64.
//   S = QK^T 3-product fp16 split (near-fp32 exact), fp32 softmax on frags,
//   P fp16, O = P*(Vh+Vl) 2-product. V stored transposed in smem.
// ---------------------------------------------------------------------------
#define AROWB 144
#define APLANE (64 * AROWB)              // 9216 B
#define ATTN_SMEM (6 * APLANE)           // Qh Ql Kh Kl Vh Vl = 55296 B

__global__ void __launch_bounds__(128) attn_kernel()
{
    extern __shared__ char asm_raw[];
    const uint32_t sQh = smem_u32(asm_raw);
    const uint32_t sQl = sQh + APLANE;
    const uint32_t sKh = sQh + 2 * APLANE;
    const uint32_t sKl = sQh + 3 * APLANE;
    const uint32_t sVh = sQh + 4 * APLANE;   // transposed: [d][seq]
    const uint32_t sVl = sQh + 5 * APLANE;

    const int tid = threadIdx.x;
    int idx = blockIdx.x;
    const int axis = idx / (BB * WW * GRP);
    idx -= axis * (BB * WW * GRP);
    const int b     = idx / (WW * GRP);
    int rem         = idx - b * (WW * GRP);
    const int fixed = rem / GRP;
    const int n     = rem - fixed * GRP;

    size_t base;
    int stride;
    if (axis == 0) {
        base   = ((size_t)b * HH * WW + fixed) * CC + n * 64;
        stride = WW * CC;
    } else {
        base   = ((size_t)(b * HH + fixed)) * (size_t)(WW * CC) + (n + GRP) * 64;
        stride = CC;
    }

    // Load fp32 q/k/v, convert to fp16 hi/lo, store to smem.
    // 1024 float4 units; 128 threads -> 8 each.
    for (int t = tid; t < 1024; t += 128) {
        int i = t >> 4, d = (t & 15) * 4;
        size_t off = base + (size_t)i * stride + d;
        float4 q4 = *(const float4*)(g_q + off);
        float4 k4 = *(const float4*)(g_k + off);
        float4 v4 = *(const float4*)(g_v + off);
        uint32_t rowoff = (uint32_t)(i * AROWB + d * 2);
        // Q
        {
            __half h0 = __float2half_rn(q4.x), h1 = __float2half_rn(q4.y);
            __half h2 = __float2half_rn(q4.z), h3 = __float2half_rn(q4.w);
            __half l0 = __float2half_rn(q4.x - __half2float(h0));
            __half l1 = __float2half_rn(q4.y - __half2float(h1));
            __half l2 = __float2half_rn(q4.z - __half2float(h2));
            __half l3 = __float2half_rn(q4.w - __half2float(h3));
            uint32_t p0 = packh(h0, h1), p1 = packh(h2, h3);
            asm volatile("st.shared.v2.b32 [%0], {%1,%2};" :: "r"(sQh + rowoff), "r"(p0), "r"(p1) : "memory");
            p0 = packh(l0, l1); p1 = packh(l2, l3);
            asm volatile("st.shared.v2.b32 [%0], {%1,%2};" :: "r"(sQl + rowoff), "r"(p0), "r"(p1) : "memory");
        }
        // K
        {
            __half h0 = __float2half_rn(k4.x), h1 = __float2half_rn(k4.y);
            __half h2 = __float2half_rn(k4.z), h3 = __float2half_rn(k4.w);
            __half l0 = __float2half_rn(k4.x - __half2float(h0));
            __half l1 = __float2half_rn(k4.y - __half2float(h1));
            __half l2 = __float2half_rn(k4.z - __half2float(h2));
            __half l3 = __float2half_rn(k4.w - __half2float(h3));
            uint32_t p0 = packh(h0, h1), p1 = packh(h2, h3);
            asm volatile("st.shared.v2.b32 [%0], {%1,%2};" :: "r"(sKh + rowoff), "r"(p0), "r"(p1) : "memory");
            p0 = packh(l0, l1); p1 = packh(l2, l3);
            asm volatile("st.shared.v2.b32 [%0], {%1,%2};" :: "r"(sKl + rowoff), "r"(p0), "r"(p1) : "memory");
        }
        // V transposed: smem[d+z][i]
        const float* vp = &v4.x;
        #pragma unroll
        for (int z = 0; z < 4; z++) {
            float v = vp[z];
            __half h = __float2half_rn(v);
            __half l = __float2half_rn(v - __half2float(h));
            uint32_t toff = (uint32_t)((d + z) * AROWB + i * 2);
            asm volatile("st.shared.b16 [%0], %1;" :: "r"(sVh + toff), "h"(__half_as_ushort(h)) : "memory");
            asm volatile("st.shared.b16 [%0], %1;" :: "r"(sVl + toff), "h"(__half_as_ushort(l)) : "memory");
        }
    }
    __syncthreads();

    const int lane = tid & 31;
    const int wid  = tid >> 5;                 // 4 warps: rows wid*16..+15
    const int a_row = wid * 16 + (lane & 15);
    const int a_k   = lane >> 4;
    const int b_row = (lane & 7) | ((lane >> 4) << 3);
    const int b_k   = (lane >> 3) & 1;

    // ---- S = Q K^T (3-product) ----
    float s[8][4];
    #pragma unroll
    for (int nt = 0; nt < 8; nt++)
        #pragma unroll
        for (int e = 0; e < 4; e++) s[nt][e] = 0.0f;

    #pragma unroll
    for (int ks = 0; ks < 4; ks++) {
        uint32_t ah[4], al[4];
        uint32_t ad = (uint32_t)(a_row * AROWB + (ks * 2 + a_k) * 16);
        ldsm4(ah, sQh + ad);
        ldsm4(al, sQl + ad);
        #pragma unroll
        for (int np = 0; np < 4; np++) {
            uint32_t bd = (uint32_t)((b_row + np * 16) * AROWB + (ks * 2 + b_k) * 16);
            uint32_t rh[4], rl[4];
            ldsm4(rh, sKh + bd);
            ldsm4(rl, sKl + bd);
            mma16816(s[np * 2],     ah, rh);
            mma16816(s[np * 2],     al, rh);
            mma16816(s[np * 2],     ah, rl);
            mma16816(s[np * 2 + 1], ah, rh + 2);
            mma16816(s[np * 2 + 1], al, rh + 2);
            mma16816(s[np * 2 + 1], ah, rl + 2);
        }
    }

    // ---- softmax (fp32, per fragment rows r0=lane>>2 and r0+8) ----
    float m0 = -1e30f, m1 = -1e30f;
    #pragma unroll
    for (int nt = 0; nt < 8; nt++) {
        m0 = fmaxf(m0, fmaxf(s[nt][0], s[nt][1]));
        m1 = fmaxf(m1, fmaxf(s[nt][2], s[nt][3]));
    }
    #pragma unroll
    for (int o = 1; o <= 2; o <<= 1) {
        m0 = fmaxf(m0, __shfl_xor_sync(0xffffffffu, m0, o));
        m1 = fmaxf(m1, __shfl_xor_sync(0xffffffffu, m1, o));
    }
    float sum0 = 0.0f, sum1 = 0.0f;
    #pragma unroll
    for (int nt = 0; nt < 8; nt++) {
        s[nt][0] = __expf((s[nt][0] - m0) * INV_SCALE);
        s[nt][1] = __expf((s[nt][1] - m0) * INV_SCALE);
        s[nt][2] = __expf((s[nt][2] - m1) * INV_SCALE);
        s[nt][3] = __expf((s[nt][3] - m1) * INV_SCALE);
        sum0 += s[nt][0] + s[nt][1];
        sum1 += s[nt][2] + s[nt][3];
    }
    #pragma unroll
    for (int o = 1; o <= 2; o <<= 1) {
        sum0 += __shfl_xor_sync(0xffffffffu, sum0, o);
        sum1 += __shfl_xor_sync(0xffffffffu, sum1, o);
    }
    float inv0 = 1.0f / sum0, inv1 = 1.0f / sum1;

    // pack P into A-fragments: pa[j] covers seq cols 16j..16j+15
    uint32_t pa[4][4];
    #pragma unroll
    for (int j = 0; j < 4; j++) {
        pa[j][0] = packh(__float2half_rn(s[2 * j][0] * inv0),
                         __float2half_rn(s[2 * j][1] * inv0));
        pa[j][1] = packh(__float2half_rn(s[2 * j][2] * inv1),
                         __float2half_rn(s[2 * j][3] * inv1));
        pa[j][2] = packh(__float2half_rn(s[2 * j + 1][0] * inv0),
                         __float2half_rn(s[2 * j + 1][1] * inv0));
        pa[j][3] = packh(__float2half_rn(s[2 * j + 1][2] * inv1),
                         __float2half_rn(s[2 * j + 1][3] * inv1));
    }

    // ---- O = P V (2-product over V hi/lo); B from transposed V planes ----
    float o_[8][4];
    #pragma unroll
    for (int nt = 0; nt < 8; nt++)
        #pragma unroll
        for (int e = 0; e < 4; e++) o_[nt][e] = 0.0f;

    #pragma unroll
    for (int j = 0; j < 4; j++) {
        #pragma unroll
        for (int np = 0; np < 4; np++) {
            uint32_t bd = (uint32_t)((b_row + np * 16) * AROWB + (j * 2 + b_k) * 16);
            uint32_t rh[4], rl[4];
            ldsm4(rh, sVh + bd);
            ldsm4(rl, sVl + bd);
            mma16816(o_[np * 2],     pa[j], rh);
            mma16816(o_[np * 2],     pa[j], rl);
            mma16816(o_[np * 2 + 1], pa[j], rh + 2);
            mma16816(o_[np * 2 + 1], pa[j], rl + 2);
        }
    }

    // ---- write fp16 hi/lo attention output ----
    const int r0 = lane >> 2;
    const int c0 = (lane & 3) * 2;
    #pragma unroll
    for (int nt = 0; nt < 8; nt++) {
        int d = nt * 8 + c0;
        int i0_ = wid * 16 + r0;
        size_t off0 = base + (size_t)i0_ * stride + d;
        size_t off1 = base + (size_t)(i0_ + 8) * stride + d;
        __half h0 = __float2half_rn(o_[nt][0]);
        __half h1 = __float2half_rn(o_[nt][1]);
        __half l0 = __float2half_rn(o_[nt][0] - __half2float(h0));
        __half l1 = __float2half_rn(o_[nt][1] - __half2float(h1));
        *(uint32_t*)(g_ah + off0) = packh(h0, h1);
        *(uint32_t*)(g_al + off0) = packh(l0, l1);
        __half h2 = __float2half_rn(o_[nt][2]);
        __half h3 = __float2half_rn(o_[nt][3]);
        __half l2 = __float2half_rn(o_[nt][2] - __half2float(h2));
        __half l3 = __float2half_rn(o_[nt][3] - __half2float(h3));
        *(uint32_t*)(g_ah + off1) = packh(h2, h3);
        *(uint32_t*)(g_al + off1) = packh(l2, l3);
    }
}

// ---------------------------------------------------------------------------
extern "C" void kernel_launch(void* const* d_in, const int* in_sizes, int n_in,
                              void* d_out, int out_size)
{
    const float* queries = (const float*)d_in[0];
    const float* values  = (const float*)d_in[1];
    const float* Wq = (const float*)d_in[2];
    const float* bq = (const float*)d_in[3];
    const float* Wk = (const float*)d_in[4];
    const float* bk = (const float*)d_in[5];
    const float* Wv = (const float*)d_in[6];
    const float* bv = (const float*)d_in[7];
    const float* Wo = (const float*)d_in[8];
    const float* bo = (const float*)d_in[9];
    float* out = (float*)d_out;

    float *qp, *kp, *vp;
    __half *qh, *ql, *vh, *vl, *ah, *al, *wt;
    cudaGetSymbolAddress((void**)&qp, g_q);
    cudaGetSymbolAddress((void**)&kp, g_k);
    cudaGetSymbolAddress((void**)&vp, g_v);
    cudaGetSymbolAddress((void**)&qh, g_qh);
    cudaGetSymbolAddress((void**)&ql, g_ql);
    cudaGetSymbolAddress((void**)&vh, g_vh);
    cudaGetSymbolAddress((void**)&vl, g_vl);
    cudaGetSymbolAddress((void**)&ah, g_ah);
    cudaGetSymbolAddress((void**)&al, g_al);
    cudaGetSymbolAddress((void**)&wt, g_wt);

    cudaFuncSetAttribute(attn_kernel, cudaFuncAttributeMaxDynamicSharedMemorySize,
                         ATTN_SMEM);
    cudaFuncSetAttribute(gemm_f16s, cudaFuncAttributeMaxDynamicSharedMemorySize,
                         GEMM_SMEM);

    const int n4 = MTOT * CC / 4;

    // weight transpose + fp16 (launches 0-3)
    dim3 wtg(CC / 32, CC / 32), wtb(32, 8);
    __half* WqT = wt + 0 * (size_t)CC * CC;
    __half* WkT = wt + 1 * (size_t)CC * CC;
    __half* WvT = wt + 2 * (size_t)CC * CC;
    __half* WoT = wt + 3 * (size_t)CC * CC;
    wt_conv<<<wtg, wtb>>>(Wq, WqT);
    wt_conv<<<wtg, wtb>>>(Wk, WkT);
    wt_conv<<<wtg, wtb>>>(Wv, WvT);
    wt_conv<<<wtg, wtb>>>(Wo, WoT);

    // input split conversions (both tensors, one launch)
    conv_split2<<<(2 * n4 + 255) / 256, 256>>>(
        (const float4*)queries, (uint2*)qh, (uint2*)ql,
        (const float4*)values,  (uint2*)vh, (uint2*)vl, n4);

    // Q, K, V projections fused into one launch (3 segments)
    GemmSeg sq = {qh, ql, WqT, bq, qp};
    GemmSeg sk = {vh, vl, WkT, bk, kp};
    GemmSeg sv = {vh, vl, WvT, bv, vp};
    dim3 g3(3 * NBX, MTOT / 256);
    gemm_f16s<<<g3, 256, GEMM_SMEM>>>(sq, sk, sv);

    attn_kernel<<<2 * BB * WW * GRP, 128, ATTN_SMEM>>>();

    // output projection
    GemmSeg so = {ah, al, WoT, bo, out};
    dim3 g1(NBX, MTOT / 256);
    gemm_f16s<<<g1, 256, GEMM_SMEM>>>(so, so, so);
}